// round 6
// baseline (speedup 1.0000x reference)
#include <cuda_runtime.h>
#include <math.h>
#include <stdint.h>

#define MAX_N 100000
#define MAX_E 600000

__device__ float g_QU  [(size_t)MAX_N * 384];  // q(128)|u0(128)|u1(128)
__device__ float g_KV  [(size_t)MAX_N * 256];  // k(128)|v(128)
__device__ float g_acc [(size_t)MAX_N * 256];  // normalized e-accumulators per head
__device__ float g_BcatT[768 * 128];           // [n][k]
__device__ float g_bcat[768];
__device__ float g_BblkT[128 * 256];           // [n][k]
__device__ int  g_cnt[MAX_N];
__device__ int  g_off[MAX_N];
__device__ int  g_cur[MAX_N];
__device__ int  g_bsum[256];
__device__ int2 g_edges[MAX_E];

// ---------------------------------------------------------------------------
// Common PTX helpers
// ---------------------------------------------------------------------------
__device__ __forceinline__ void cpz(unsigned dst, const void* src, int sz) {
    asm volatile("cp.async.cg.shared.global [%0], [%1], 16, %2;"
                 :: "r"(dst), "l"(src), "r"(sz));
}
__device__ __forceinline__ uint32_t to_tf32(float x) {
    uint32_t u; asm("cvt.rna.tf32.f32 %0, %1;" : "=r"(u) : "f"(x)); return u;
}
__device__ __forceinline__ void mma8(float* c, const uint32_t* a, const uint32_t* b) {
    asm volatile("mma.sync.aligned.m16n8k8.row.col.f32.tf32.tf32.f32 "
        "{%0,%1,%2,%3}, {%4,%5,%6,%7}, {%8,%9}, {%0,%1,%2,%3};"
        : "+f"(c[0]), "+f"(c[1]), "+f"(c[2]), "+f"(c[3])
        : "r"(a[0]), "r"(a[1]), "r"(a[2]), "r"(a[3]), "r"(b[0]), "r"(b[1]));
}

// ---------------------------------------------------------------------------
// Projection GEMM with A-reuse: A tile (128 x 128) resident in smem as tf32,
// loops over NB 128-col B tiles (double-buffered, converted once per tile).
// Split write: cols 0..383 -> g_QU, 384..639 -> g_KV, 640..767 -> out.
// Dynamic smem: As 128x132 u32 (67.5KB) + Bs[2][128][132] f32 (135KB).
// ---------------------------------------------------------------------------
__global__ __launch_bounds__(256) void mma_proj(
    const float* __restrict__ A,
    const float* __restrict__ BT,
    float* __restrict__ C,
    int M, const float* __restrict__ bias, int NB)
{
    extern __shared__ char sm_[];
    uint32_t (*As)[132] = (uint32_t(*)[132])sm_;
    float (*Bs)[128][132] = (float(*)[128][132])(sm_ + 128 * 132 * 4);

    const int tid = threadIdx.x;
    const int lane = tid & 31;
    const int warp = tid >> 5;
    const int wm = warp & 3, wn = warp >> 2;
    const int grp = lane >> 2, qd = lane & 3;
    const int bm0 = blockIdx.x * 128;

    // full 128x128 tile = 4096 16B-chunks -> 16 iterations of 256 threads
    auto cpB = [&](int bn, int buf) {
#pragma unroll
        for (int i = 0; i < 16; i++) {
            int idx = tid + 256 * i;
            int row = idx >> 5, ch = (idx & 31) * 4;
            const float* src = BT + (size_t)(bn * 128 + row) * 128 + ch;
            unsigned dst = (unsigned)__cvta_generic_to_shared(&Bs[buf][row][ch]);
            cpz(dst, src, 16);
        }
        asm volatile("cp.async.commit_group;");
    };

    // Load A tile (zero-fill rows >= M via sz=0) + first B tile
#pragma unroll
    for (int i = 0; i < 16; i++) {
        int idx = tid + 256 * i;
        int row = idx >> 5, ch = (idx & 31) * 4;
        int gr = bm0 + row;
        int grc = gr < M ? gr : (M - 1);
        const float* src = A + (size_t)grc * 128 + ch;
        unsigned dst = (unsigned)__cvta_generic_to_shared(&As[row][ch]);
        cpz(dst, src, gr < M ? 16 : 0);
    }
    cpB(0, 0);
    asm volatile("cp.async.wait_group 0;");
    __syncthreads();

    // Convert A to tf32 in place
#pragma unroll
    for (int i = 0; i < 16; i++) {
        int idx = tid + 256 * i;               // 4096 float4
        int row = idx >> 5, c4 = (idx & 31) * 4;
        float4 v = *(const float4*)&((const float*)As)[row * 132 + c4];
        uint32_t* p = &As[row][c4];
        p[0] = to_tf32(v.x); p[1] = to_tf32(v.y);
        p[2] = to_tf32(v.z); p[3] = to_tf32(v.w);
    }

    for (int bn = 0; bn < NB; bn++) {
        int buf = bn & 1;
        asm volatile("cp.async.wait_group 0;");
        __syncthreads();

        // Convert this B tile to tf32 in place
#pragma unroll
        for (int i = 0; i < 16; i++) {
            int idx = tid + 256 * i;
            int row = idx >> 5, c4 = (idx & 31) * 4;
            float4 v = *(const float4*)&Bs[buf][row][c4];
            uint32_t* p = (uint32_t*)&Bs[buf][row][c4];
            p[0] = to_tf32(v.x); p[1] = to_tf32(v.y);
            p[2] = to_tf32(v.z); p[3] = to_tf32(v.w);
        }
        __syncthreads();

        if (bn + 1 < NB) cpB(bn + 1, buf ^ 1);   // overlap next load with MMA

        float c[2][8][4];
#pragma unroll
        for (int i = 0; i < 2; i++)
#pragma unroll
            for (int j = 0; j < 8; j++)
#pragma unroll
                for (int u = 0; u < 4; u++) c[i][j][u] = 0.f;

        const uint32_t (*Bsc)[132] = (const uint32_t(*)[132])Bs[buf];
#pragma unroll
        for (int kt = 0; kt < 8; kt++) {
#pragma unroll
            for (int k8 = 0; k8 < 2; k8++) {
                int k0 = kt * 16 + k8 * 8;
                uint32_t af[2][4], bf[8][2];
#pragma unroll
                for (int mt = 0; mt < 2; mt++) {
                    int mr = wm * 32 + mt * 16 + grp;
                    af[mt][0] = As[mr    ][k0 + qd];
                    af[mt][1] = As[mr + 8][k0 + qd];
                    af[mt][2] = As[mr    ][k0 + qd + 4];
                    af[mt][3] = As[mr + 8][k0 + qd + 4];
                }
#pragma unroll
                for (int nt = 0; nt < 8; nt++) {
                    int nr = wn * 64 + nt * 8 + grp;
                    bf[nt][0] = Bsc[nr][k0 + qd];
                    bf[nt][1] = Bsc[nr][k0 + qd + 4];
                }
#pragma unroll
                for (int mt = 0; mt < 2; mt++)
#pragma unroll
                    for (int nt = 0; nt < 8; nt++)
                        mma8(c[mt][nt], af[mt], bf[nt]);
            }
        }

        // epilogue for this bn
#pragma unroll
        for (int mt = 0; mt < 2; mt++)
#pragma unroll
            for (int nt = 0; nt < 8; nt++)
#pragma unroll
                for (int hf = 0; hf < 2; hf++) {
                    int row = bm0 + wm * 32 + mt * 16 + grp + hf * 8;
                    if (row >= M) continue;
                    int col = bn * 128 + wn * 64 + nt * 8 + qd * 2;
#pragma unroll
                    for (int u = 0; u < 2; u++) {
                        int cc = col + u;
                        float v = c[mt][nt][hf * 2 + u] + bias[cc];
                        float* cp;
                        if (cc < 384)      cp = &g_QU[(size_t)row * 384 + cc];
                        else if (cc < 640) cp = &g_KV[(size_t)row * 256 + (cc - 384)];
                        else               cp = &C[(size_t)row * 128 + (cc - 640)];
                        *cp = v;
                    }
                }
        __syncthreads();
    }
}

// ---------------------------------------------------------------------------
// Generic tf32 GEMM (epilogue): C[M x 128] += A[M x K] @ B, BT[n][k].
// ---------------------------------------------------------------------------
__global__ __launch_bounds__(256) void mma_gemm(
    const float* __restrict__ A, int lda,
    const float* __restrict__ BT, int ldb,
    float* __restrict__ C,
    int M, int K)
{
    __shared__ float As[2][128][20];
    __shared__ float Bs[2][128][20];
    const int tid = threadIdx.x;
    const int lane = tid & 31;
    const int warp = tid >> 5;
    const int wm = warp & 3, wn = warp >> 2;
    const int grp = lane >> 2, qd = lane & 3;
    const int bm0 = blockIdx.x * 128;

    float c[2][8][4];
#pragma unroll
    for (int i = 0; i < 2; i++)
#pragma unroll
        for (int j = 0; j < 8; j++)
#pragma unroll
            for (int u = 0; u < 4; u++) c[i][j][u] = 0.f;

    const int ntiles = K >> 4;

    auto cpA = [&](int kt, int buf) {
#pragma unroll
        for (int it = 0; it < 2; it++) {
            int idx = tid + 256 * it;
            int row = idx >> 2, ch = (idx & 3) * 4;
            int gr = bm0 + row;
            int grc = gr < M ? gr : (M - 1);
            const float* src = A + (size_t)grc * lda + kt * 16 + ch;
            unsigned dst = (unsigned)__cvta_generic_to_shared(&As[buf][row][ch]);
            cpz(dst, src, gr < M ? 16 : 0);
        }
    };
    auto cpB = [&](int kt, int buf) {
#pragma unroll
        for (int it = 0; it < 2; it++) {
            int idx = tid + 256 * it;
            int row = idx >> 2, ch = (idx & 3) * 4;
            const float* src = BT + (size_t)row * ldb + kt * 16 + ch;
            unsigned dst = (unsigned)__cvta_generic_to_shared(&Bs[buf][row][ch]);
            cpz(dst, src, 16);
        }
    };

    cpA(0, 0); cpB(0, 0);
    asm volatile("cp.async.commit_group;");
    asm volatile("cp.async.wait_group 0;");
    __syncthreads();

    for (int t = 0; t < ntiles; t++) {
        int cur = t & 1, nxt = cur ^ 1;
        bool more = (t + 1 < ntiles);
        if (more) {
            cpA(t + 1, nxt); cpB(t + 1, nxt);
            asm volatile("cp.async.commit_group;");
        }
#pragma unroll
        for (int k8 = 0; k8 < 2; k8++) {
            int k0 = k8 * 8;
            uint32_t af[2][4], bf[8][2];
#pragma unroll
            for (int mt = 0; mt < 2; mt++) {
                int mr = wm * 32 + mt * 16 + grp;
                af[mt][0] = to_tf32(As[cur][mr    ][k0 + qd]);
                af[mt][1] = to_tf32(As[cur][mr + 8][k0 + qd]);
                af[mt][2] = to_tf32(As[cur][mr    ][k0 + qd + 4]);
                af[mt][3] = to_tf32(As[cur][mr + 8][k0 + qd + 4]);
            }
#pragma unroll
            for (int nt = 0; nt < 8; nt++) {
                int nr = wn * 64 + nt * 8 + grp;
                bf[nt][0] = to_tf32(Bs[cur][nr][k0 + qd]);
                bf[nt][1] = to_tf32(Bs[cur][nr][k0 + qd + 4]);
            }
#pragma unroll
            for (int mt = 0; mt < 2; mt++)
#pragma unroll
                for (int nt = 0; nt < 8; nt++)
                    mma8(c[mt][nt], af[mt], bf[nt]);
        }
        if (more) asm volatile("cp.async.wait_group 0;");
        __syncthreads();
    }

#pragma unroll
    for (int mt = 0; mt < 2; mt++)
#pragma unroll
        for (int nt = 0; nt < 8; nt++)
#pragma unroll
            for (int hf = 0; hf < 2; hf++) {
                int row = bm0 + wm * 32 + mt * 16 + grp + hf * 8;
                if (row >= M) continue;
                int col = wn * 64 + nt * 8 + qd * 2;
#pragma unroll
                for (int u = 0; u < 2; u++) {
                    float* cp = &C[(size_t)row * 128 + col + u];
                    *cp += c[mt][nt][hf * 2 + u];
                }
            }
}

// ---------------------------------------------------------------------------
// Prep kernels
// ---------------------------------------------------------------------------
__global__ __launch_bounds__(128) void prep_bcat(
    const float* __restrict__ Wq, const float* __restrict__ bq,
    const float* __restrict__ Wk, const float* __restrict__ bk,
    const float* __restrict__ Wv, const float* __restrict__ bv,
    const float* __restrict__ Ws, const float* __restrict__ bs,
    const float* __restrict__ We, int N)
{
    for (int i = blockIdx.x * 128 + threadIdx.x; i < N; i += 768 * 128)
        g_cnt[i] = 0;

    int j = blockIdx.x;      // output col 0..767
    int r = threadIdx.x;     // k row 0..127
    float v;
    if (j < 128) v = Wq[r * 128 + j];
    else if (j < 256) {
        int d = j - 128; const float* w = We + d * 128;
        float s = 0.f;
#pragma unroll
        for (int c = 0; c < 64; c++) s = fmaf(Wq[r * 128 + c], w[c], s);
        v = s;
    } else if (j < 384) {
        int d = j - 256; const float* w = We + d * 128 + 64;
        float s = 0.f;
#pragma unroll
        for (int c = 0; c < 64; c++) s = fmaf(Wq[r * 128 + 64 + c], w[c], s);
        v = s;
    }
    else if (j < 512) v = Wk[r * 128 + (j - 384)];
    else if (j < 640) v = Wv[r * 128 + (j - 512)];
    else              v = Ws[r * 128 + (j - 640)];
    g_BcatT[j * 128 + r] = v;

    if (r == 0) {
        float bv2;
        if (j < 128) bv2 = bq[j];
        else if (j < 256) {
            int d = j - 128; const float* w = We + d * 128;
            float s = 0.f;
            for (int c = 0; c < 64; c++) s = fmaf(bq[c], w[c], s);
            bv2 = s;
        } else if (j < 384) {
            int d = j - 256; const float* w = We + d * 128 + 64;
            float s = 0.f;
            for (int c = 0; c < 64; c++) s = fmaf(bq[64 + c], w[c], s);
            bv2 = s;
        }
        else if (j < 512) bv2 = bk[j - 384];
        else if (j < 640) bv2 = bv[j - 512];
        else              bv2 = bs[j - 640];
        g_bcat[j] = bv2;
    }
}

__global__ __launch_bounds__(256) void prep_bblk(const float* __restrict__ We)
{
    int n = blockIdx.x;      // 0..127
    int k = threadIdx.x;     // 0..255
    float v = 0.f;
    if (k < 128) { if (n < 64)  v = We[k * 128 + n]; }
    else         { if (n >= 64) v = We[(k - 128) * 128 + n]; }
    g_BblkT[n * 256 + k] = v;
}

// ---------------------------------------------------------------------------
// Edge binning (counting sort by dst)
// ---------------------------------------------------------------------------
__global__ __launch_bounds__(256) void hist_k(const int* __restrict__ ei, int E)
{
    int i = blockIdx.x * 256 + threadIdx.x;
    if (i < E) atomicAdd(&g_cnt[ei[E + i]], 1);
}

__global__ __launch_bounds__(512) void scan1_k(int N)
{
    __shared__ int sh[512];
    int tid = threadIdx.x;
    int i = blockIdx.x * 512 + tid;
    int v = (i < N) ? g_cnt[i] : 0;
    sh[tid] = v;
    __syncthreads();
#pragma unroll
    for (int o = 1; o < 512; o <<= 1) {
        int t = (tid >= o) ? sh[tid - o] : 0;
        __syncthreads();
        sh[tid] += t;
        __syncthreads();
    }
    if (i < N) g_off[i] = sh[tid] - v;
    if (tid == 511) g_bsum[blockIdx.x] = sh[511];
}

__global__ __launch_bounds__(256) void scan2_k(int nb)
{
    __shared__ int sh[256];
    int tid = threadIdx.x;
    int v = (tid < nb) ? g_bsum[tid] : 0;
    sh[tid] = v;
    __syncthreads();
#pragma unroll
    for (int o = 1; o < 256; o <<= 1) {
        int t = (tid >= o) ? sh[tid - o] : 0;
        __syncthreads();
        sh[tid] += t;
        __syncthreads();
    }
    if (tid < nb) g_bsum[tid] = sh[tid] - v;
}

__global__ __launch_bounds__(512) void scan3_k(int N)
{
    int i = blockIdx.x * 512 + threadIdx.x;
    if (i < N) {
        int o = g_off[i] + g_bsum[i >> 9];
        g_off[i] = o;
        g_cur[i] = o;
    }
}

__global__ __launch_bounds__(256) void scatter_k(const int* __restrict__ ei, int E)
{
    int e = blockIdx.x * 256 + threadIdx.x;
    if (e >= E) return;
    int dst = ei[E + e];
    int pos = atomicAdd(&g_cur[dst], 1);
    g_edges[pos] = make_int2(ei[e], e);
}

// ---------------------------------------------------------------------------
// Aggregation: warp per dst node, 16 lanes per edge, 2 edges per iteration.
// ---------------------------------------------------------------------------
__device__ __forceinline__ float coss(float x) {
    float k = rintf(x * 0.15915494309189535f);
    float r = fmaf(k, -6.28125f, x);
    r = fmaf(k, -1.93530717958623e-3f, r);
    return __cosf(r);
}
__device__ __forceinline__ float dot4(float4 a, float4 b) {
    return a.x * b.x + a.y * b.y + a.z * b.z + a.w * b.w;
}
__device__ __forceinline__ float4 fma4(float s, float4 a, float4 acc) {
    acc.x = fmaf(s, a.x, acc.x);
    acc.y = fmaf(s, a.y, acc.y);
    acc.z = fmaf(s, a.z, acc.z);
    acc.w = fmaf(s, a.w, acc.w);
    return acc;
}
__device__ __forceinline__ float4 xadd16(float4 v) {
    v.x += __shfl_xor_sync(0xffffffffu, v.x, 16);
    v.y += __shfl_xor_sync(0xffffffffu, v.y, 16);
    v.z += __shfl_xor_sync(0xffffffffu, v.z, 16);
    v.w += __shfl_xor_sync(0xffffffffu, v.w, 16);
    return v;
}

__global__ __launch_bounds__(256) void agg_k(
    const float* __restrict__ lu, const float* __restrict__ tt,
    const float* __restrict__ msg,
    const float* __restrict__ wt, const float* __restrict__ bt,
    float* __restrict__ out, int N)
{
    int n = (int)((blockIdx.x * 256 + threadIdx.x) >> 5);
    int lane = threadIdx.x & 31;
    if (n >= N) return;
    int half = lane >> 4, sl = lane & 15;

    int off = g_off[n];
    int deg = g_cnt[n];

    const float4* QU4 = (const float4*)(g_QU + (size_t)n * 384);
    float4 qa  = QU4[2 * sl],      qb  = QU4[2 * sl + 1];
    float4 u0a = QU4[32 + 2 * sl], u0b = QU4[33 + 2 * sl];
    float4 u1a = QU4[64 + 2 * sl], u1b = QU4[65 + 2 * sl];

    float4 wa = make_float4(0, 0, 0, 0), wb = wa, ba = wa, bb = wa;
    if (sl < 8) {
        wa = ((const float4*)wt)[2 * sl]; wb = ((const float4*)wt)[2 * sl + 1];
        ba = ((const float4*)bt)[2 * sl]; bb = ((const float4*)bt)[2 * sl + 1];
    }

    float4 z = make_float4(0, 0, 0, 0);
    float4 ava = z, avb = z, A0a = z, A0b = z, A1a = z, A1b = z;
    float den0 = 0.f, den1 = 0.f;

    int nit = (deg + 1) >> 1;

    int2 se = make_int2(0, 0);
    float lus = 0.f, tts = 0.f;
    float4 ka = z, kb = z, va = z, vb = z, ma = z, mb = z;
    bool v_cur = false;
    if (nit > 0) {
        int idx = half;
        v_cur = idx < deg;
        int ec = off + (v_cur ? idx : 0);
        se = g_edges[ec];
        lus = lu[se.x]; tts = tt[se.y];
        const float4* KV4 = (const float4*)(g_KV + (size_t)se.x * 256);
        ka = KV4[2 * sl]; kb = KV4[2 * sl + 1];
        va = KV4[32 + 2 * sl]; vb = KV4[33 + 2 * sl];
        if (sl >= 8) {
            const float4* M4 = (const float4*)(msg + (size_t)se.y * 64);
            ma = M4[2 * sl - 16]; mb = M4[2 * sl - 15];
        }
    }

    for (int it = 0; it < nit; it++) {
        // stage next pair
        bool v_nxt = false;
        int2 se2 = se; float lus2 = 0.f, tts2 = 0.f;
        float4 ka2 = z, kb2 = z, va2 = z, vb2 = z, ma2 = z, mb2 = z;
        if (it + 1 < nit) {
            int idx = 2 * (it + 1) + half;
            v_nxt = idx < deg;
            int ec = off + (v_nxt ? idx : deg - 1);
            se2 = g_edges[ec];
            lus2 = lu[se2.x]; tts2 = tt[se2.y];
            const float4* KV4 = (const float4*)(g_KV + (size_t)se2.x * 256);
            ka2 = KV4[2 * sl]; kb2 = KV4[2 * sl + 1];
            va2 = KV4[32 + 2 * sl]; vb2 = KV4[33 + 2 * sl];
            if (sl >= 8) {
                const float4* M4 = (const float4*)(msg + (size_t)se2.y * 64);
                ma2 = M4[2 * sl - 16]; mb2 = M4[2 * sl - 15];
            }
        }

        float relt = lus - tts;
        float4 ea_a, ea_b;
        if (sl < 8) {
            ea_a.x = coss(fmaf(relt, wa.x, ba.x));
            ea_a.y = coss(fmaf(relt, wa.y, ba.y));
            ea_a.z = coss(fmaf(relt, wa.z, ba.z));
            ea_a.w = coss(fmaf(relt, wa.w, ba.w));
            ea_b.x = coss(fmaf(relt, wb.x, bb.x));
            ea_b.y = coss(fmaf(relt, wb.y, bb.y));
            ea_b.z = coss(fmaf(relt, wb.z, bb.z));
            ea_b.w = coss(fmaf(relt, wb.w, bb.w));
        } else {
            ea_a = ma; ea_b = mb;
        }

        float pqk = dot4(qa, ka) + dot4(qb, kb);
        float s0 = dot4(ea_a, u0a) + dot4(ea_b, u0b) + (sl < 8 ? pqk : 0.f);
        float s1 = dot4(ea_a, u1a) + dot4(ea_b, u1b) + (sl < 8 ? 0.f : pqk);
#pragma unroll
        for (int o = 8; o; o >>= 1) {
            s0 += __shfl_xor_sync(0xffffffffu, s0, o);
            s1 += __shfl_xor_sync(0xffffffffu, s1, o);
        }

        float ex0 = v_cur ? __expf(s0 * 0.125f) : 0.f;
        float ex1 = v_cur ? __expf(s1 * 0.125f) : 0.f;
        den0 += ex0;
        den1 += ex1;

        float evv = (sl < 8) ? ex0 : ex1;
        ava = fma4(evv, va, ava);
        avb = fma4(evv, vb, avb);
        A0a = fma4(ex0, ea_a, A0a);
        A0b = fma4(ex0, ea_b, A0b);
        A1a = fma4(ex1, ea_a, A1a);
        A1b = fma4(ex1, ea_b, A1b);

        v_cur = v_nxt; se = se2; lus = lus2; tts = tts2;
        ka = ka2; kb = kb2; va = va2; vb = vb2; ma = ma2; mb = mb2;
    }

    // merge edge-parity halves (each half covers all 128 channels)
    den0 += __shfl_xor_sync(0xffffffffu, den0, 16);
    den1 += __shfl_xor_sync(0xffffffffu, den1, 16);
    ava = xadd16(ava); avb = xadd16(avb);
    A0a = xadd16(A0a); A0b = xadd16(A0b);
    A1a = xadd16(A1a); A1b = xadd16(A1b);

    float inv0 = 1.f / (den0 + 1e-16f);
    float inv1 = 1.f / (den1 + 1e-16f);

    if (half == 0) {
        float invv = (sl < 8) ? inv0 : inv1;
        float4* op = ((float4*)out) + (size_t)n * 32;
        float4 o1 = op[2 * sl], o2 = op[2 * sl + 1];
        o1.x += ava.x * invv; o1.y += ava.y * invv;
        o1.z += ava.z * invv; o1.w += ava.w * invv;
        o2.x += avb.x * invv; o2.y += avb.y * invv;
        o2.z += avb.z * invv; o2.w += avb.w * invv;
        op[2 * sl] = o1; op[2 * sl + 1] = o2;

        A0a.x *= inv0; A0a.y *= inv0; A0a.z *= inv0; A0a.w *= inv0;
        A0b.x *= inv0; A0b.y *= inv0; A0b.z *= inv0; A0b.w *= inv0;
        A1a.x *= inv1; A1a.y *= inv1; A1a.z *= inv1; A1a.w *= inv1;
        A1b.x *= inv1; A1b.y *= inv1; A1b.z *= inv1; A1b.w *= inv1;
        float4* acc4 = (float4*)(g_acc + (size_t)n * 256);
        acc4[2 * sl]      = A0a;
        acc4[2 * sl + 1]  = A0b;
        acc4[32 + 2 * sl] = A1a;
        acc4[33 + 2 * sl] = A1b;
    }
}

// ---------------------------------------------------------------------------
extern "C" void kernel_launch(void* const* d_in, const int* in_sizes, int n_in,
                              void* d_out, int out_size)
{
    const float* x    = (const float*)d_in[0];
    const float* lu   = (const float*)d_in[1];
    const int*   ei   = (const int*)  d_in[2];
    const float* tt   = (const float*)d_in[3];
    const float* msg  = (const float*)d_in[4];
    const float* wt   = (const float*)d_in[5];
    const float* bt   = (const float*)d_in[6];
    const float* Wq   = (const float*)d_in[7];
    const float* bq   = (const float*)d_in[8];
    const float* Wk   = (const float*)d_in[9];
    const float* bk   = (const float*)d_in[10];
    const float* Wv   = (const float*)d_in[11];
    const float* bv   = (const float*)d_in[12];
    const float* We   = (const float*)d_in[13];
    const float* Ws   = (const float*)d_in[14];
    const float* bs   = (const float*)d_in[15];
    float* out = (float*)d_out;

    int N = in_sizes[1];
    int E = in_sizes[3];

    float *pacc, *pBcatT, *pbcat, *pBblkT;
    cudaGetSymbolAddress((void**)&pacc,   g_acc);
    cudaGetSymbolAddress((void**)&pBcatT, g_BcatT);
    cudaGetSymbolAddress((void**)&pbcat,  g_bcat);
    cudaGetSymbolAddress((void**)&pBblkT, g_BblkT);

    const int PROJ_SMEM = 128 * 132 * 4 + 2 * 128 * 132 * 4;   // 202752 B
    cudaFuncSetAttribute(mma_proj, cudaFuncAttributeMaxDynamicSharedMemorySize,
                         PROJ_SMEM);

    int gm = (N + 127) / 128;
    int nb = (N + 511) / 512;

    prep_bcat<<<768, 128>>>(Wq, bq, Wk, bk, Wv, bv, Ws, bs, We, N);
    prep_bblk<<<128, 256>>>(We);
    hist_k<<<(E + 255) / 256, 256>>>(ei, E);
    scan1_k<<<nb, 512>>>(N);
    scan2_k<<<1, 256>>>(nb);
    scan3_k<<<nb, 512>>>(N);
    scatter_k<<<(E + 255) / 256, 256>>>(ei, E);

    // Projection (tf32, A-resident): [q|u0|u1|k|v|skip] = x @ Bcat + bcat
    mma_proj<<<gm, 256, PROJ_SMEM>>>(x, pBcatT, out, N, pbcat, 6);

    // Aggregation (warp per dst, 2 edges/iter), adds v-part into out
    agg_k<<<(N + 7) / 8, 256>>>(lu, tt, msg, wt, bt, out, N);

    // Epilogue (tf32): out += accE[N x 256] @ Bblk[256 x 128]
    mma_gemm<<<gm, 256>>>(pacc, 256, pBblkT, 256, out, N, 256);
}

// round 7
// speedup vs baseline: 1.7713x; 1.7713x over previous
#include <cuda_runtime.h>
#include <math.h>
#include <stdint.h>

#define MAX_N 100000
#define MAX_E 600000

__device__ float g_QU  [(size_t)MAX_N * 384];  // q(128)|u0(128)|u1(128)
__device__ float g_KV  [(size_t)MAX_N * 256];  // k(128)|v(128)
__device__ float g_acc [(size_t)MAX_N * 256];  // normalized e-accumulators (tf32-rounded)
__device__ float g_BcatT[768 * 128];           // [n][k], tf32-rounded
__device__ float g_bcat[768];
__device__ float g_BblkT[128 * 256];           // [n][k], tf32-rounded
__device__ int  g_cnt[MAX_N];
__device__ int  g_off[MAX_N];
__device__ int  g_cur[MAX_N];
__device__ int  g_bsum[256];
__device__ int2 g_edges[MAX_E];

// ---------------------------------------------------------------------------
// PTX helpers
// ---------------------------------------------------------------------------
__device__ __forceinline__ void cpz(unsigned dst, const void* src, int sz) {
    asm volatile("cp.async.cg.shared.global [%0], [%1], 16, %2;"
                 :: "r"(dst), "l"(src), "r"(sz));
}
__device__ __forceinline__ uint32_t to_tf32(float x) {
    uint32_t u; asm("cvt.rna.tf32.f32 %0, %1;" : "=r"(u) : "f"(x)); return u;
}
__device__ __forceinline__ void mma8(float* c, const uint32_t* a, const uint32_t* b) {
    asm volatile("mma.sync.aligned.m16n8k8.row.col.f32.tf32.tf32.f32 "
        "{%0,%1,%2,%3}, {%4,%5,%6,%7}, {%8,%9}, {%0,%1,%2,%3};"
        : "+f"(c[0]), "+f"(c[1]), "+f"(c[2]), "+f"(c[3])
        : "r"(a[0]), "r"(a[1]), "r"(a[2]), "r"(a[3]), "r"(b[0]), "r"(b[1]));
}

// ---------------------------------------------------------------------------
// tf32 GEMM (R4-proven shape). C[M x (128*gridDim.y)] = A[M x K] @ B (+bias)(+=C)
// BM=128, BN=128, BK=16, 256 thr (8 warps, 4x2), warp tile 64x64, m16n8k8.
// BT[n][k] pre-rounded to tf32 (loaded raw). cvtA: round A fragments (1) or
// pass raw (0, when A is already tf32-rounded). mode==1: split projection write.
// ---------------------------------------------------------------------------
__global__ __launch_bounds__(256) void mma_gemm(
    const float* __restrict__ A, int lda,
    const float* __restrict__ BT, int ldb,
    float* __restrict__ C,
    int M, int K,
    const float* __restrict__ bias, int accum, int mode, int cvtA)
{
    __shared__ float As[2][128][20];
    __shared__ float Bs[2][128][20];
    const int tid = threadIdx.x;
    const int lane = tid & 31;
    const int warp = tid >> 5;
    const int wm = warp & 3, wn = warp >> 2;
    const int grp = lane >> 2, qd = lane & 3;
    const int bm0 = blockIdx.x * 128;
    const int bn0 = blockIdx.y * 128;

    float c[2][8][4];
#pragma unroll
    for (int i = 0; i < 2; i++)
#pragma unroll
        for (int j = 0; j < 8; j++)
#pragma unroll
            for (int u = 0; u < 4; u++) c[i][j][u] = 0.f;

    const int ntiles = K >> 4;

    auto cpA = [&](int kt, int buf) {
#pragma unroll
        for (int it = 0; it < 2; it++) {
            int idx = tid + 256 * it;
            int row = idx >> 2, ch = (idx & 3) * 4;
            int gr = bm0 + row;
            int grc = gr < M ? gr : (M - 1);
            const float* src = A + (size_t)grc * lda + kt * 16 + ch;
            unsigned dst = (unsigned)__cvta_generic_to_shared(&As[buf][row][ch]);
            cpz(dst, src, gr < M ? 16 : 0);
        }
    };
    auto cpB = [&](int kt, int buf) {
#pragma unroll
        for (int it = 0; it < 2; it++) {
            int idx = tid + 256 * it;
            int row = idx >> 2, ch = (idx & 3) * 4;
            const float* src = BT + (size_t)(bn0 + row) * ldb + kt * 16 + ch;
            unsigned dst = (unsigned)__cvta_generic_to_shared(&Bs[buf][row][ch]);
            cpz(dst, src, 16);
        }
    };

    cpA(0, 0); cpB(0, 0);
    asm volatile("cp.async.commit_group;");
    asm volatile("cp.async.wait_group 0;");
    __syncthreads();

    for (int t = 0; t < ntiles; t++) {
        int cur = t & 1, nxt = cur ^ 1;
        bool more = (t + 1 < ntiles);
        if (more) {
            cpA(t + 1, nxt); cpB(t + 1, nxt);
            asm volatile("cp.async.commit_group;");
        }
#pragma unroll
        for (int k8 = 0; k8 < 2; k8++) {
            int k0 = k8 * 8;
            uint32_t af[2][4], bf[8][2];
#pragma unroll
            for (int mt = 0; mt < 2; mt++) {
                int mr = wm * 32 + mt * 16 + grp;
                if (cvtA) {
                    af[mt][0] = to_tf32(As[cur][mr    ][k0 + qd]);
                    af[mt][1] = to_tf32(As[cur][mr + 8][k0 + qd]);
                    af[mt][2] = to_tf32(As[cur][mr    ][k0 + qd + 4]);
                    af[mt][3] = to_tf32(As[cur][mr + 8][k0 + qd + 4]);
                } else {
                    af[mt][0] = __float_as_uint(As[cur][mr    ][k0 + qd]);
                    af[mt][1] = __float_as_uint(As[cur][mr + 8][k0 + qd]);
                    af[mt][2] = __float_as_uint(As[cur][mr    ][k0 + qd + 4]);
                    af[mt][3] = __float_as_uint(As[cur][mr + 8][k0 + qd + 4]);
                }
            }
#pragma unroll
            for (int nt = 0; nt < 8; nt++) {
                int nr = wn * 64 + nt * 8 + grp;
                bf[nt][0] = __float_as_uint(Bs[cur][nr][k0 + qd]);
                bf[nt][1] = __float_as_uint(Bs[cur][nr][k0 + qd + 4]);
            }
#pragma unroll
            for (int mt = 0; mt < 2; mt++)
#pragma unroll
                for (int nt = 0; nt < 8; nt++)
                    mma8(c[mt][nt], af[mt], bf[nt]);
        }
        if (more) asm volatile("cp.async.wait_group 0;");
        __syncthreads();
    }

#pragma unroll
    for (int mt = 0; mt < 2; mt++)
#pragma unroll
        for (int nt = 0; nt < 8; nt++)
#pragma unroll
            for (int hf = 0; hf < 2; hf++) {
                int row = bm0 + wm * 32 + mt * 16 + grp + hf * 8;
                if (row >= M) continue;
                int col = bn0 + wn * 64 + nt * 8 + qd * 2;
#pragma unroll
                for (int u = 0; u < 2; u++) {
                    float v = c[mt][nt][hf * 2 + u];
                    int cc = col + u;
                    if (bias) v += bias[cc];
                    float* cp;
                    if (mode == 0)       cp = &C[(size_t)row * 128 + cc];
                    else if (cc < 384)   cp = &g_QU[(size_t)row * 384 + cc];
                    else if (cc < 640)   cp = &g_KV[(size_t)row * 256 + (cc - 384)];
                    else                 cp = &C[(size_t)row * 128 + (cc - 640)];
                    if (accum) v += *cp;
                    *cp = v;
                }
            }
}

// ---------------------------------------------------------------------------
// Prep kernels (weights stored tf32-pre-rounded)
// ---------------------------------------------------------------------------
__global__ __launch_bounds__(128) void prep_bcat(
    const float* __restrict__ Wq, const float* __restrict__ bq,
    const float* __restrict__ Wk, const float* __restrict__ bk,
    const float* __restrict__ Wv, const float* __restrict__ bv,
    const float* __restrict__ Ws, const float* __restrict__ bs,
    const float* __restrict__ We, int N)
{
    for (int i = blockIdx.x * 128 + threadIdx.x; i < N; i += 768 * 128)
        g_cnt[i] = 0;

    int j = blockIdx.x;      // output col 0..767
    int r = threadIdx.x;     // k row 0..127
    float v;
    if (j < 128) v = Wq[r * 128 + j];
    else if (j < 256) {
        int d = j - 128; const float* w = We + d * 128;
        float s = 0.f;
#pragma unroll
        for (int c = 0; c < 64; c++) s = fmaf(Wq[r * 128 + c], w[c], s);
        v = s;
    } else if (j < 384) {
        int d = j - 256; const float* w = We + d * 128 + 64;
        float s = 0.f;
#pragma unroll
        for (int c = 0; c < 64; c++) s = fmaf(Wq[r * 128 + 64 + c], w[c], s);
        v = s;
    }
    else if (j < 512) v = Wk[r * 128 + (j - 384)];
    else if (j < 640) v = Wv[r * 128 + (j - 512)];
    else              v = Ws[r * 128 + (j - 640)];
    g_BcatT[j * 128 + r] = __uint_as_float(to_tf32(v));

    if (r == 0) {
        float bv2;
        if (j < 128) bv2 = bq[j];
        else if (j < 256) {
            int d = j - 128; const float* w = We + d * 128;
            float s = 0.f;
            for (int c = 0; c < 64; c++) s = fmaf(bq[c], w[c], s);
            bv2 = s;
        } else if (j < 384) {
            int d = j - 256; const float* w = We + d * 128 + 64;
            float s = 0.f;
            for (int c = 0; c < 64; c++) s = fmaf(bq[64 + c], w[c], s);
            bv2 = s;
        }
        else if (j < 512) bv2 = bk[j - 384];
        else if (j < 640) bv2 = bv[j - 512];
        else              bv2 = bs[j - 640];
        g_bcat[j] = bv2;
    }
}

__global__ __launch_bounds__(256) void prep_bblk(const float* __restrict__ We)
{
    int n = blockIdx.x;      // 0..127
    int k = threadIdx.x;     // 0..255
    float v = 0.f;
    if (k < 128) { if (n < 64)  v = We[k * 128 + n]; }
    else         { if (n >= 64) v = We[(k - 128) * 128 + n]; }
    g_BblkT[n * 256 + k] = __uint_as_float(to_tf32(v));
}

// ---------------------------------------------------------------------------
// Edge binning (counting sort by dst)
// ---------------------------------------------------------------------------
__global__ __launch_bounds__(256) void hist_k(const int* __restrict__ ei, int E)
{
    int i = blockIdx.x * 256 + threadIdx.x;
    if (i < E) atomicAdd(&g_cnt[ei[E + i]], 1);
}

__global__ __launch_bounds__(512) void scan1_k(int N)
{
    __shared__ int sh[512];
    int tid = threadIdx.x;
    int i = blockIdx.x * 512 + tid;
    int v = (i < N) ? g_cnt[i] : 0;
    sh[tid] = v;
    __syncthreads();
#pragma unroll
    for (int o = 1; o < 512; o <<= 1) {
        int t = (tid >= o) ? sh[tid - o] : 0;
        __syncthreads();
        sh[tid] += t;
        __syncthreads();
    }
    if (i < N) g_off[i] = sh[tid] - v;
    if (tid == 511) g_bsum[blockIdx.x] = sh[511];
}

__global__ __launch_bounds__(256) void scan2_k(int nb)
{
    __shared__ int sh[256];
    int tid = threadIdx.x;
    int v = (tid < nb) ? g_bsum[tid] : 0;
    sh[tid] = v;
    __syncthreads();
#pragma unroll
    for (int o = 1; o < 256; o <<= 1) {
        int t = (tid >= o) ? sh[tid - o] : 0;
        __syncthreads();
        sh[tid] += t;
        __syncthreads();
    }
    if (tid < nb) g_bsum[tid] = sh[tid] - v;
}

__global__ __launch_bounds__(512) void scan3_k(int N)
{
    int i = blockIdx.x * 512 + threadIdx.x;
    if (i < N) {
        int o = g_off[i] + g_bsum[i >> 9];
        g_off[i] = o;
        g_cur[i] = o;
    }
}

__global__ __launch_bounds__(256) void scatter_k(const int* __restrict__ ei, int E)
{
    int e = blockIdx.x * 256 + threadIdx.x;
    if (e >= E) return;
    int dst = ei[E + e];
    int pos = atomicAdd(&g_cur[dst], 1);
    g_edges[pos] = make_int2(ei[e], e);
}

// ---------------------------------------------------------------------------
// Aggregation: warp per dst node (R4-proven), streamed data via __ldcs so the
// randomly-gathered g_KV stays L2-resident.
// ---------------------------------------------------------------------------
__device__ __forceinline__ float coss(float x) {
    float k = rintf(x * 0.15915494309189535f);
    float r = fmaf(k, -6.28125f, x);
    r = fmaf(k, -1.93530717958623e-3f, r);
    return __cosf(r);
}
__device__ __forceinline__ float dot4(float4 a, float4 b) {
    return a.x * b.x + a.y * b.y + a.z * b.z + a.w * b.w;
}
__device__ __forceinline__ float4 fma4(float s, float4 a, float4 acc) {
    acc.x = fmaf(s, a.x, acc.x);
    acc.y = fmaf(s, a.y, acc.y);
    acc.z = fmaf(s, a.z, acc.z);
    acc.w = fmaf(s, a.w, acc.w);
    return acc;
}

__global__ __launch_bounds__(256) void agg_k(
    const float* __restrict__ lu, const float* __restrict__ tt,
    const float* __restrict__ msg,
    const float* __restrict__ wt, const float* __restrict__ bt,
    float* __restrict__ out, int N)
{
    int n = (int)((blockIdx.x * 256 + threadIdx.x) >> 5);
    int lane = threadIdx.x & 31;
    if (n >= N) return;

    int off = g_off[n];
    int deg = g_cnt[n];

    const float4* QU4 = (const float4*)(g_QU + (size_t)n * 384);
    float4 q4 = QU4[lane];
    float4 u0 = QU4[32 + lane];
    float4 u1 = QU4[64 + lane];

    float4 w4 = make_float4(0.f, 0.f, 0.f, 0.f), b4 = w4;
    if (lane < 16) {
        w4 = ((const float4*)wt)[lane];
        b4 = ((const float4*)bt)[lane];
    }

    float4 av = make_float4(0.f, 0.f, 0.f, 0.f);
    float4 A0 = av, A1 = av;
    float den0 = 0.f, den1 = 0.f;

    int2 se = make_int2(0, 0);
    float lus = 0.f, tts = 0.f;
    float4 kk = av, vv = av, mg = av;
    if (deg > 0) {
        se = __ldcs(&g_edges[off]);
        lus = lu[se.x]; tts = __ldcs(&tt[se.y]);
        const float4* KV4 = (const float4*)(g_KV + (size_t)se.x * 256);
        kk = KV4[lane]; vv = KV4[32 + lane];
        if (lane >= 16) mg = __ldcs(((const float4*)(msg + (size_t)se.y * 64)) + (lane - 16));
    }

    for (int i = 0; i < deg; i++) {
        // stage next edge (loads overlap with the reduction below)
        int2 se2 = se; float lus2 = 0.f, tts2 = 0.f;
        float4 kk2 = av, vv2 = av, mg2 = av;
        bool more = (i + 1 < deg);
        if (more) {
            se2 = __ldcs(&g_edges[off + i + 1]);
            lus2 = lu[se2.x]; tts2 = __ldcs(&tt[se2.y]);
            const float4* KV4 = (const float4*)(g_KV + (size_t)se2.x * 256);
            kk2 = KV4[lane]; vv2 = KV4[32 + lane];
            if (lane >= 16) mg2 = __ldcs(((const float4*)(msg + (size_t)se2.y * 64)) + (lane - 16));
        }

        float relt = lus - tts;
        float4 ea;
        if (lane < 16) {
            ea.x = coss(fmaf(relt, w4.x, b4.x));
            ea.y = coss(fmaf(relt, w4.y, b4.y));
            ea.z = coss(fmaf(relt, w4.z, b4.z));
            ea.w = coss(fmaf(relt, w4.w, b4.w));
        } else {
            ea = mg;
        }

        float pqk = dot4(q4, kk);
        float s0 = dot4(ea, u0) + (lane < 16 ? pqk : 0.f);
        float s1 = dot4(ea, u1) + (lane < 16 ? 0.f : pqk);
#pragma unroll
        for (int o = 16; o; o >>= 1) {
            s0 += __shfl_xor_sync(0xffffffffu, s0, o);
            s1 += __shfl_xor_sync(0xffffffffu, s1, o);
        }

        float ex0 = __expf(s0 * 0.125f);
        float ex1 = __expf(s1 * 0.125f);
        den0 += ex0;
        den1 += ex1;

        float evv = (lane < 16) ? ex0 : ex1;
        av = fma4(evv, vv, av);
        A0 = fma4(ex0, ea, A0);
        A1 = fma4(ex1, ea, A1);

        se = se2; lus = lus2; tts = tts2; kk = kk2; vv = vv2; mg = mg2;
    }

    float inv0 = 1.f / (den0 + 1e-16f);
    float inv1 = 1.f / (den1 + 1e-16f);
    float invv = (lane < 16) ? inv0 : inv1;

    // out already holds skip; add normalized v-part (sole writer per row)
    float4* op = ((float4*)out) + (size_t)n * 32 + lane;
    float4 o = *op;
    o.x += av.x * invv; o.y += av.y * invv;
    o.z += av.z * invv; o.w += av.w * invv;
    *op = o;

    // store e-accumulators tf32-pre-rounded (epilogue GEMM runs cvtA=0)
    float4 W0, W1;
    W0.x = __uint_as_float(to_tf32(A0.x * inv0));
    W0.y = __uint_as_float(to_tf32(A0.y * inv0));
    W0.z = __uint_as_float(to_tf32(A0.z * inv0));
    W0.w = __uint_as_float(to_tf32(A0.w * inv0));
    W1.x = __uint_as_float(to_tf32(A1.x * inv1));
    W1.y = __uint_as_float(to_tf32(A1.y * inv1));
    W1.z = __uint_as_float(to_tf32(A1.z * inv1));
    W1.w = __uint_as_float(to_tf32(A1.w * inv1));
    float4* acc4 = (float4*)(g_acc + (size_t)n * 256);
    acc4[lane]      = W0;
    acc4[32 + lane] = W1;
}

// ---------------------------------------------------------------------------
extern "C" void kernel_launch(void* const* d_in, const int* in_sizes, int n_in,
                              void* d_out, int out_size)
{
    const float* x    = (const float*)d_in[0];
    const float* lu   = (const float*)d_in[1];
    const int*   ei   = (const int*)  d_in[2];
    const float* tt   = (const float*)d_in[3];
    const float* msg  = (const float*)d_in[4];
    const float* wt   = (const float*)d_in[5];
    const float* bt   = (const float*)d_in[6];
    const float* Wq   = (const float*)d_in[7];
    const float* bq   = (const float*)d_in[8];
    const float* Wk   = (const float*)d_in[9];
    const float* bk   = (const float*)d_in[10];
    const float* Wv   = (const float*)d_in[11];
    const float* bv   = (const float*)d_in[12];
    const float* We   = (const float*)d_in[13];
    const float* Ws   = (const float*)d_in[14];
    const float* bs   = (const float*)d_in[15];
    float* out = (float*)d_out;

    int N = in_sizes[1];
    int E = in_sizes[3];

    float *pacc, *pBcatT, *pbcat, *pBblkT;
    cudaGetSymbolAddress((void**)&pacc,   g_acc);
    cudaGetSymbolAddress((void**)&pBcatT, g_BcatT);
    cudaGetSymbolAddress((void**)&pbcat,  g_bcat);
    cudaGetSymbolAddress((void**)&pBblkT, g_BblkT);

    int gm = (N + 127) / 128;
    int nb = (N + 511) / 512;

    prep_bcat<<<768, 128>>>(Wq, bq, Wk, bk, Wv, bv, Ws, bs, We, N);
    prep_bblk<<<128, 256>>>(We);
    hist_k<<<(E + 255) / 256, 256>>>(ei, E);
    scan1_k<<<nb, 512>>>(N);
    scan2_k<<<1, 256>>>(nb);
    scan3_k<<<nb, 512>>>(N);
    scatter_k<<<(E + 255) / 256, 256>>>(ei, E);

    // Projection (tf32): [q|u0|u1|k|v|skip] = x @ Bcat + bcat  (split write)
    mma_gemm<<<dim3(gm, 6), 256>>>(x, 128, pBcatT, 128, out, N, 128,
                                   pbcat, 0, 1, 1);

    // Aggregation (warp per dst node), adds v-part into out
    agg_k<<<(N + 7) / 8, 256>>>(lu, tt, msg, wt, bt, out, N);

    // Epilogue (tf32, no cvt): out += accE[N x 256] @ Bblk[256 x 128]
    mma_gemm<<<dim3(gm, 1), 256>>>(pacc, 256, pBblkT, 256, out, N, 256,
                                   nullptr, 1, 0, 0);
}

// round 8
// speedup vs baseline: 1.8577x; 1.0488x over previous
#include <cuda_runtime.h>
#include <math.h>
#include <stdint.h>

#define MAX_N 100000
#define MAX_E 600000

__device__ float g_QU  [(size_t)MAX_N * 384];  // q(128)|u0(128)|u1(128)
__device__ float g_KV  [(size_t)MAX_N * 256];  // k(128)|v(128)
__device__ float g_acc [(size_t)MAX_N * 256];  // normalized e-accumulators (tf32-rounded)
__device__ float g_BcatT[768 * 128];           // [n][k], tf32-rounded
__device__ float g_bcat[768];
__device__ float g_BblkT[128 * 256];           // [n][k], tf32-rounded
__device__ int  g_cnt[MAX_N];
__device__ int  g_off[MAX_N];
__device__ int  g_cur[MAX_N];
__device__ int  g_bsum[256];
__device__ int2 g_edges[MAX_E];

// ---------------------------------------------------------------------------
// PTX helpers
// ---------------------------------------------------------------------------
__device__ __forceinline__ void cpz(unsigned dst, const void* src, int sz) {
    asm volatile("cp.async.cg.shared.global [%0], [%1], 16, %2;"
                 :: "r"(dst), "l"(src), "r"(sz));
}
__device__ __forceinline__ uint32_t to_tf32(float x) {
    uint32_t u; asm("cvt.rna.tf32.f32 %0, %1;" : "=r"(u) : "f"(x)); return u;
}
__device__ __forceinline__ void mma8(float* c, const uint32_t* a, const uint32_t* b) {
    asm volatile("mma.sync.aligned.m16n8k8.row.col.f32.tf32.tf32.f32 "
        "{%0,%1,%2,%3}, {%4,%5,%6,%7}, {%8,%9}, {%0,%1,%2,%3};"
        : "+f"(c[0]), "+f"(c[1]), "+f"(c[2]), "+f"(c[3])
        : "r"(a[0]), "r"(a[1]), "r"(a[2]), "r"(a[3]), "r"(b[0]), "r"(b[1]));
}

// ---------------------------------------------------------------------------
// tf32 GEMM (R4-proven shape). C[M x (128*gridDim.y)] = A[M x K] @ B (+bias)(+=C)
// BM=128, BN=128, BK=16, 256 thr (8 warps, 4x2), warp tile 64x64, m16n8k8.
// BT[n][k] pre-rounded tf32 (loaded raw). cvtA rounds A fragments when A is raw
// fp32. mode==1: split projection write (QU/KV/out).
// ---------------------------------------------------------------------------
__global__ __launch_bounds__(256) void mma_gemm(
    const float* __restrict__ A, int lda,
    const float* __restrict__ BT, int ldb,
    float* __restrict__ C,
    int M, int K,
    const float* __restrict__ bias, int accum, int mode, int cvtA)
{
    __shared__ float As[2][128][20];
    __shared__ float Bs[2][128][20];
    const int tid = threadIdx.x;
    const int lane = tid & 31;
    const int warp = tid >> 5;
    const int wm = warp & 3, wn = warp >> 2;
    const int grp = lane >> 2, qd = lane & 3;
    const int bm0 = blockIdx.x * 128;
    const int bn0 = blockIdx.y * 128;

    float c[2][8][4];
#pragma unroll
    for (int i = 0; i < 2; i++)
#pragma unroll
        for (int j = 0; j < 8; j++)
#pragma unroll
            for (int u = 0; u < 4; u++) c[i][j][u] = 0.f;

    const int ntiles = K >> 4;

    auto cpA = [&](int kt, int buf) {
#pragma unroll
        for (int it = 0; it < 2; it++) {
            int idx = tid + 256 * it;
            int row = idx >> 2, ch = (idx & 3) * 4;
            int gr = bm0 + row;
            int grc = gr < M ? gr : (M - 1);
            const float* src = A + (size_t)grc * lda + kt * 16 + ch;
            unsigned dst = (unsigned)__cvta_generic_to_shared(&As[buf][row][ch]);
            cpz(dst, src, gr < M ? 16 : 0);
        }
    };
    auto cpB = [&](int kt, int buf) {
#pragma unroll
        for (int it = 0; it < 2; it++) {
            int idx = tid + 256 * it;
            int row = idx >> 2, ch = (idx & 3) * 4;
            const float* src = BT + (size_t)(bn0 + row) * ldb + kt * 16 + ch;
            unsigned dst = (unsigned)__cvta_generic_to_shared(&Bs[buf][row][ch]);
            cpz(dst, src, 16);
        }
    };

    cpA(0, 0); cpB(0, 0);
    asm volatile("cp.async.commit_group;");
    asm volatile("cp.async.wait_group 0;");
    __syncthreads();

    for (int t = 0; t < ntiles; t++) {
        int cur = t & 1, nxt = cur ^ 1;
        bool more = (t + 1 < ntiles);
        if (more) {
            cpA(t + 1, nxt); cpB(t + 1, nxt);
            asm volatile("cp.async.commit_group;");
        }
#pragma unroll
        for (int k8 = 0; k8 < 2; k8++) {
            int k0 = k8 * 8;
            uint32_t af[2][4], bf[8][2];
#pragma unroll
            for (int mt = 0; mt < 2; mt++) {
                int mr = wm * 32 + mt * 16 + grp;
                if (cvtA) {
                    af[mt][0] = to_tf32(As[cur][mr    ][k0 + qd]);
                    af[mt][1] = to_tf32(As[cur][mr + 8][k0 + qd]);
                    af[mt][2] = to_tf32(As[cur][mr    ][k0 + qd + 4]);
                    af[mt][3] = to_tf32(As[cur][mr + 8][k0 + qd + 4]);
                } else {
                    af[mt][0] = __float_as_uint(As[cur][mr    ][k0 + qd]);
                    af[mt][1] = __float_as_uint(As[cur][mr + 8][k0 + qd]);
                    af[mt][2] = __float_as_uint(As[cur][mr    ][k0 + qd + 4]);
                    af[mt][3] = __float_as_uint(As[cur][mr + 8][k0 + qd + 4]);
                }
            }
#pragma unroll
            for (int nt = 0; nt < 8; nt++) {
                int nr = wn * 64 + nt * 8 + grp;
                bf[nt][0] = __float_as_uint(Bs[cur][nr][k0 + qd]);
                bf[nt][1] = __float_as_uint(Bs[cur][nr][k0 + qd + 4]);
            }
#pragma unroll
            for (int mt = 0; mt < 2; mt++)
#pragma unroll
                for (int nt = 0; nt < 8; nt++)
                    mma8(c[mt][nt], af[mt], bf[nt]);
        }
        if (more) asm volatile("cp.async.wait_group 0;");
        __syncthreads();
    }

#pragma unroll
    for (int mt = 0; mt < 2; mt++)
#pragma unroll
        for (int nt = 0; nt < 8; nt++)
#pragma unroll
            for (int hf = 0; hf < 2; hf++) {
                int row = bm0 + wm * 32 + mt * 16 + grp + hf * 8;
                if (row >= M) continue;
                int col = bn0 + wn * 64 + nt * 8 + qd * 2;
#pragma unroll
                for (int u = 0; u < 2; u++) {
                    float v = c[mt][nt][hf * 2 + u];
                    int cc = col + u;
                    if (bias) v += bias[cc];
                    float* cp;
                    if (mode == 0)       cp = &C[(size_t)row * 128 + cc];
                    else if (cc < 384)   cp = &g_QU[(size_t)row * 384 + cc];
                    else if (cc < 640)   cp = &g_KV[(size_t)row * 256 + (cc - 384)];
                    else                 cp = &C[(size_t)row * 128 + (cc - 640)];
                    if (accum) v += *cp;
                    *cp = v;
                }
            }
}

// ---------------------------------------------------------------------------
// Fused prep kernel: blocks 0..767 build BcatT column j (+bias), blocks
// 768..895 build BblkT row (j-768). Also zeroes g_cnt and g_cur.
// ---------------------------------------------------------------------------
__global__ __launch_bounds__(128) void prep_k(
    const float* __restrict__ Wq, const float* __restrict__ bq,
    const float* __restrict__ Wk, const float* __restrict__ bk,
    const float* __restrict__ Wv, const float* __restrict__ bv,
    const float* __restrict__ Ws, const float* __restrict__ bs,
    const float* __restrict__ We, int N)
{
    int j = blockIdx.x;
    int r = threadIdx.x;

    for (int i = j * 128 + r; i < N; i += 896 * 128) {
        g_cnt[i] = 0;
        g_cur[i] = 0;
    }

    if (j >= 768) {
        int n = j - 768;   // 0..127
#pragma unroll
        for (int kq = 0; kq < 2; kq++) {
            int k = r + kq * 128;   // 0..255
            float v = 0.f;
            if (k < 128) { if (n < 64)  v = We[k * 128 + n]; }
            else         { if (n >= 64) v = We[(k - 128) * 128 + n]; }
            g_BblkT[n * 256 + k] = __uint_as_float(to_tf32(v));
        }
        return;
    }

    float v;
    if (j < 128) v = Wq[r * 128 + j];
    else if (j < 256) {
        int d = j - 128; const float* w = We + d * 128;
        float s = 0.f;
#pragma unroll
        for (int c = 0; c < 64; c++) s = fmaf(Wq[r * 128 + c], w[c], s);
        v = s;
    } else if (j < 384) {
        int d = j - 256; const float* w = We + d * 128 + 64;
        float s = 0.f;
#pragma unroll
        for (int c = 0; c < 64; c++) s = fmaf(Wq[r * 128 + 64 + c], w[c], s);
        v = s;
    }
    else if (j < 512) v = Wk[r * 128 + (j - 384)];
    else if (j < 640) v = Wv[r * 128 + (j - 512)];
    else              v = Ws[r * 128 + (j - 640)];
    g_BcatT[j * 128 + r] = __uint_as_float(to_tf32(v));

    if (r == 0) {
        float bv2;
        if (j < 128) bv2 = bq[j];
        else if (j < 256) {
            int d = j - 128; const float* w = We + d * 128;
            float s = 0.f;
            for (int c = 0; c < 64; c++) s = fmaf(bq[c], w[c], s);
            bv2 = s;
        } else if (j < 384) {
            int d = j - 256; const float* w = We + d * 128 + 64;
            float s = 0.f;
            for (int c = 0; c < 64; c++) s = fmaf(bq[64 + c], w[c], s);
            bv2 = s;
        }
        else if (j < 512) bv2 = bk[j - 384];
        else if (j < 640) bv2 = bv[j - 512];
        else              bv2 = bs[j - 640];
        g_bcat[j] = bv2;
    }
}

// ---------------------------------------------------------------------------
// Edge binning (counting sort by dst) — no scan3: block offset folded in.
// ---------------------------------------------------------------------------
__global__ __launch_bounds__(256) void hist_k(const int* __restrict__ ei, int E)
{
    int i = blockIdx.x * 256 + threadIdx.x;
    if (i < E) atomicAdd(&g_cnt[ei[E + i]], 1);
}

__global__ __launch_bounds__(512) void scan1_k(int N)
{
    __shared__ int sh[512];
    int tid = threadIdx.x;
    int i = blockIdx.x * 512 + tid;
    int v = (i < N) ? g_cnt[i] : 0;
    sh[tid] = v;
    __syncthreads();
#pragma unroll
    for (int o = 1; o < 512; o <<= 1) {
        int t = (tid >= o) ? sh[tid - o] : 0;
        __syncthreads();
        sh[tid] += t;
        __syncthreads();
    }
    if (i < N) g_off[i] = sh[tid] - v;        // exclusive within block
    if (tid == 511) g_bsum[blockIdx.x] = sh[511];
}

__global__ __launch_bounds__(256) void scan2_k(int nb)
{
    __shared__ int sh[256];
    int tid = threadIdx.x;
    int v = (tid < nb) ? g_bsum[tid] : 0;
    sh[tid] = v;
    __syncthreads();
#pragma unroll
    for (int o = 1; o < 256; o <<= 1) {
        int t = (tid >= o) ? sh[tid - o] : 0;
        __syncthreads();
        sh[tid] += t;
        __syncthreads();
    }
    if (tid < nb) g_bsum[tid] = sh[tid] - v;  // exclusive block offsets
}

__global__ __launch_bounds__(256) void scatter_k(const int* __restrict__ ei, int E)
{
    int e = blockIdx.x * 256 + threadIdx.x;
    if (e >= E) return;
    int dst = ei[E + e];
    int base = g_off[dst] + g_bsum[dst >> 9];
    int pos = base + atomicAdd(&g_cur[dst], 1);
    g_edges[pos] = make_int2(ei[e], e);
}

// ---------------------------------------------------------------------------
// Aggregation: warp per dst node (R4-proven plain loads).
// ---------------------------------------------------------------------------
__device__ __forceinline__ float coss(float x) {
    float k = rintf(x * 0.15915494309189535f);
    float r = fmaf(k, -6.28125f, x);
    r = fmaf(k, -1.93530717958623e-3f, r);
    return __cosf(r);
}
__device__ __forceinline__ float dot4(float4 a, float4 b) {
    return a.x * b.x + a.y * b.y + a.z * b.z + a.w * b.w;
}
__device__ __forceinline__ float4 fma4(float s, float4 a, float4 acc) {
    acc.x = fmaf(s, a.x, acc.x);
    acc.y = fmaf(s, a.y, acc.y);
    acc.z = fmaf(s, a.z, acc.z);
    acc.w = fmaf(s, a.w, acc.w);
    return acc;
}

__global__ __launch_bounds__(256) void agg_k(
    const float* __restrict__ lu, const float* __restrict__ tt,
    const float* __restrict__ msg,
    const float* __restrict__ wt, const float* __restrict__ bt,
    float* __restrict__ out, int N)
{
    int n = (int)((blockIdx.x * 256 + threadIdx.x) >> 5);
    int lane = threadIdx.x & 31;
    if (n >= N) return;

    int off = g_off[n] + g_bsum[n >> 9];
    int deg = g_cnt[n];

    const float4* QU4 = (const float4*)(g_QU + (size_t)n * 384);
    float4 q4 = QU4[lane];
    float4 u0 = QU4[32 + lane];
    float4 u1 = QU4[64 + lane];

    float4 w4 = make_float4(0.f, 0.f, 0.f, 0.f), b4 = w4;
    if (lane < 16) {
        w4 = ((const float4*)wt)[lane];
        b4 = ((const float4*)bt)[lane];
    }

    float4 av = make_float4(0.f, 0.f, 0.f, 0.f);
    float4 A0 = av, A1 = av;
    float den0 = 0.f, den1 = 0.f;

    int2 se = make_int2(0, 0);
    float lus = 0.f, tts = 0.f;
    float4 kk = av, vv = av, mg = av;
    if (deg > 0) {
        se = g_edges[off];
        lus = lu[se.x]; tts = tt[se.y];
        const float4* KV4 = (const float4*)(g_KV + (size_t)se.x * 256);
        kk = KV4[lane]; vv = KV4[32 + lane];
        if (lane >= 16) mg = ((const float4*)(msg + (size_t)se.y * 64))[lane - 16];
    }

    for (int i = 0; i < deg; i++) {
        int2 se2 = se; float lus2 = 0.f, tts2 = 0.f;
        float4 kk2 = av, vv2 = av, mg2 = av;
        bool more = (i + 1 < deg);
        if (more) {
            se2 = g_edges[off + i + 1];
            lus2 = lu[se2.x]; tts2 = tt[se2.y];
            const float4* KV4 = (const float4*)(g_KV + (size_t)se2.x * 256);
            kk2 = KV4[lane]; vv2 = KV4[32 + lane];
            if (lane >= 16) mg2 = ((const float4*)(msg + (size_t)se2.y * 64))[lane - 16];
        }

        float relt = lus - tts;
        float4 ea;
        if (lane < 16) {
            ea.x = coss(fmaf(relt, w4.x, b4.x));
            ea.y = coss(fmaf(relt, w4.y, b4.y));
            ea.z = coss(fmaf(relt, w4.z, b4.z));
            ea.w = coss(fmaf(relt, w4.w, b4.w));
        } else {
            ea = mg;
        }

        float pqk = dot4(q4, kk);
        float s0 = dot4(ea, u0) + (lane < 16 ? pqk : 0.f);
        float s1 = dot4(ea, u1) + (lane < 16 ? 0.f : pqk);
#pragma unroll
        for (int o = 16; o; o >>= 1) {
            s0 += __shfl_xor_sync(0xffffffffu, s0, o);
            s1 += __shfl_xor_sync(0xffffffffu, s1, o);
        }

        float ex0 = __expf(s0 * 0.125f);
        float ex1 = __expf(s1 * 0.125f);
        den0 += ex0;
        den1 += ex1;

        float evv = (lane < 16) ? ex0 : ex1;
        av = fma4(evv, vv, av);
        A0 = fma4(ex0, ea, A0);
        A1 = fma4(ex1, ea, A1);

        se = se2; lus = lus2; tts = tts2; kk = kk2; vv = vv2; mg = mg2;
    }

    float inv0 = 1.f / (den0 + 1e-16f);
    float inv1 = 1.f / (den1 + 1e-16f);
    float invv = (lane < 16) ? inv0 : inv1;

    // out already holds skip; add normalized v-part (sole writer per row)
    float4* op = ((float4*)out) + (size_t)n * 32 + lane;
    float4 o = *op;
    o.x += av.x * invv; o.y += av.y * invv;
    o.z += av.z * invv; o.w += av.w * invv;
    *op = o;

    // store e-accumulators tf32-pre-rounded (epilogue GEMM runs cvtA=0)
    float4 W0, W1;
    W0.x = __uint_as_float(to_tf32(A0.x * inv0));
    W0.y = __uint_as_float(to_tf32(A0.y * inv0));
    W0.z = __uint_as_float(to_tf32(A0.z * inv0));
    W0.w = __uint_as_float(to_tf32(A0.w * inv0));
    W1.x = __uint_as_float(to_tf32(A1.x * inv1));
    W1.y = __uint_as_float(to_tf32(A1.y * inv1));
    W1.z = __uint_as_float(to_tf32(A1.z * inv1));
    W1.w = __uint_as_float(to_tf32(A1.w * inv1));
    float4* acc4 = (float4*)(g_acc + (size_t)n * 256);
    acc4[lane]      = W0;
    acc4[32 + lane] = W1;
}

// ---------------------------------------------------------------------------
extern "C" void kernel_launch(void* const* d_in, const int* in_sizes, int n_in,
                              void* d_out, int out_size)
{
    const float* x    = (const float*)d_in[0];
    const float* lu   = (const float*)d_in[1];
    const int*   ei   = (const int*)  d_in[2];
    const float* tt   = (const float*)d_in[3];
    const float* msg  = (const float*)d_in[4];
    const float* wt   = (const float*)d_in[5];
    const float* bt   = (const float*)d_in[6];
    const float* Wq   = (const float*)d_in[7];
    const float* bq   = (const float*)d_in[8];
    const float* Wk   = (const float*)d_in[9];
    const float* bk   = (const float*)d_in[10];
    const float* Wv   = (const float*)d_in[11];
    const float* bv   = (const float*)d_in[12];
    const float* We   = (const float*)d_in[13];
    const float* Ws   = (const float*)d_in[14];
    const float* bs   = (const float*)d_in[15];
    float* out = (float*)d_out;

    int N = in_sizes[1];
    int E = in_sizes[3];

    float *pacc, *pBcatT, *pbcat, *pBblkT;
    cudaGetSymbolAddress((void**)&pacc,   g_acc);
    cudaGetSymbolAddress((void**)&pBcatT, g_BcatT);
    cudaGetSymbolAddress((void**)&pbcat,  g_bcat);
    cudaGetSymbolAddress((void**)&pBblkT, g_BblkT);

    int gm = (N + 127) / 128;
    int nb = (N + 511) / 512;

    // launch order (proj at index 5 for ncu -s 5):
    prep_k<<<896, 128>>>(Wq, bq, Wk, bk, Wv, bv, Ws, bs, We, N);   // 0
    hist_k<<<(E + 255) / 256, 256>>>(ei, E);                       // 1
    scan1_k<<<nb, 512>>>(N);                                       // 2
    scan2_k<<<1, 256>>>(nb);                                       // 3
    scatter_k<<<(E + 255) / 256, 256>>>(ei, E);                    // 4
    // Projection (tf32): [q|u0|u1|k|v|skip] = x @ Bcat + bcat  (split write)
    mma_gemm<<<dim3(gm, 6), 256>>>(x, 128, pBcatT, 128, out,       // 5 (profiled)
                                   N, 128, pbcat, 0, 1, 1);
    // Aggregation (warp per dst node), adds v-part into out
    agg_k<<<(N + 7) / 8, 256>>>(lu, tt, msg, wt, bt, out, N);      // 6
    // Epilogue (tf32, CVT-free): out += accE[N x 256] @ Bblk[256 x 128]
    mma_gemm<<<dim3(gm, 1), 256>>>(pacc, 256, pBblkT, 256, out,    // 7
                                   N, 256, nullptr, 1, 0, 0);
}

// round 9
// speedup vs baseline: 2.2221x; 1.1962x over previous
#include <cuda_runtime.h>
#include <math.h>
#include <stdint.h>

#define MAX_N 100000
#define MAX_E 600000

__device__ float g_QU  [(size_t)MAX_N * 384];  // q(128)|u0(128)|u1(128)
__device__ float g_KV  [(size_t)MAX_N * 256];  // k(128)|v(128)
__device__ float g_acc [(size_t)MAX_N * 256];  // normalized e-accumulators (tf32-rounded)
__device__ float g_BcatT[768 * 128];           // [n][k], tf32-rounded
__device__ float g_bcat[768];
__device__ float g_BblkT[128 * 256];           // [n][k], tf32-rounded
__device__ int   g_cnt[MAX_N];
__device__ int   g_off[MAX_N];
__device__ int   g_cur[MAX_N];
__device__ int   g_bsum[256];
__device__ int2  g_edges[MAX_E];               // (src, e) grouped by dst
__device__ float g_relt[MAX_E];                // lu[src]-t[e], same order

// ---------------------------------------------------------------------------
// PTX helpers
// ---------------------------------------------------------------------------
__device__ __forceinline__ void cpz(unsigned dst, const void* src, int sz) {
    asm volatile("cp.async.cg.shared.global [%0], [%1], 16, %2;"
                 :: "r"(dst), "l"(src), "r"(sz));
}
__device__ __forceinline__ uint32_t to_tf32(float x) {
    uint32_t u; asm("cvt.rna.tf32.f32 %0, %1;" : "=r"(u) : "f"(x)); return u;
}
__device__ __forceinline__ void mma8(float* c, const uint32_t* a, const uint32_t* b) {
    asm volatile("mma.sync.aligned.m16n8k8.row.col.f32.tf32.tf32.f32 "
        "{%0,%1,%2,%3}, {%4,%5,%6,%7}, {%8,%9}, {%0,%1,%2,%3};"
        : "+f"(c[0]), "+f"(c[1]), "+f"(c[2]), "+f"(c[3])
        : "r"(a[0]), "r"(a[1]), "r"(a[2]), "r"(a[3]), "r"(b[0]), "r"(b[1]));
}

// ---------------------------------------------------------------------------
// tf32 GEMM. C[M x (128*gridDim.y)] = A[M x K] @ B (+bias)(+=C)
// BM=128, BN=128, BK=16, 256 thr (8 warps, 4x2), warp tile 64x64, m16n8k8.
// BT[n][k] pre-rounded tf32 (loaded raw). Split-write target resolved
// uniformly per block (region boundaries are 128-aligned).
// ---------------------------------------------------------------------------
__global__ __launch_bounds__(256) void mma_gemm(
    const float* __restrict__ A, int lda,
    const float* __restrict__ BT, int ldb,
    float* __restrict__ C,
    int M, int K,
    const float* __restrict__ bias, int accum, int mode, int cvtA)
{
    __shared__ float As[2][128][20];
    __shared__ float Bs[2][128][20];
    const int tid = threadIdx.x;
    const int lane = tid & 31;
    const int warp = tid >> 5;
    const int wm = warp & 3, wn = warp >> 2;
    const int grp = lane >> 2, qd = lane & 3;
    const int bm0 = blockIdx.x * 128;
    const int bn0 = blockIdx.y * 128;

    float c[2][8][4];
#pragma unroll
    for (int i = 0; i < 2; i++)
#pragma unroll
        for (int j = 0; j < 8; j++)
#pragma unroll
            for (int u = 0; u < 4; u++) c[i][j][u] = 0.f;

    const int ntiles = K >> 4;

    auto cpA = [&](int kt, int buf) {
#pragma unroll
        for (int it = 0; it < 2; it++) {
            int idx = tid + 256 * it;
            int row = idx >> 2, ch = (idx & 3) * 4;
            int gr = bm0 + row;
            int grc = gr < M ? gr : (M - 1);
            const float* src = A + (size_t)grc * lda + kt * 16 + ch;
            unsigned dst = (unsigned)__cvta_generic_to_shared(&As[buf][row][ch]);
            cpz(dst, src, gr < M ? 16 : 0);
        }
    };
    auto cpB = [&](int kt, int buf) {
#pragma unroll
        for (int it = 0; it < 2; it++) {
            int idx = tid + 256 * it;
            int row = idx >> 2, ch = (idx & 3) * 4;
            const float* src = BT + (size_t)(bn0 + row) * ldb + kt * 16 + ch;
            unsigned dst = (unsigned)__cvta_generic_to_shared(&Bs[buf][row][ch]);
            cpz(dst, src, 16);
        }
    };

    cpA(0, 0); cpB(0, 0);
    asm volatile("cp.async.commit_group;");
    asm volatile("cp.async.wait_group 0;");
    __syncthreads();

    for (int t = 0; t < ntiles; t++) {
        int cur = t & 1, nxt = cur ^ 1;
        bool more = (t + 1 < ntiles);
        if (more) {
            cpA(t + 1, nxt); cpB(t + 1, nxt);
            asm volatile("cp.async.commit_group;");
        }
#pragma unroll
        for (int k8 = 0; k8 < 2; k8++) {
            int k0 = k8 * 8;
            uint32_t af[2][4], bf[8][2];
#pragma unroll
            for (int mt = 0; mt < 2; mt++) {
                int mr = wm * 32 + mt * 16 + grp;
                if (cvtA) {
                    af[mt][0] = to_tf32(As[cur][mr    ][k0 + qd]);
                    af[mt][1] = to_tf32(As[cur][mr + 8][k0 + qd]);
                    af[mt][2] = to_tf32(As[cur][mr    ][k0 + qd + 4]);
                    af[mt][3] = to_tf32(As[cur][mr + 8][k0 + qd + 4]);
                } else {
                    af[mt][0] = __float_as_uint(As[cur][mr    ][k0 + qd]);
                    af[mt][1] = __float_as_uint(As[cur][mr + 8][k0 + qd]);
                    af[mt][2] = __float_as_uint(As[cur][mr    ][k0 + qd + 4]);
                    af[mt][3] = __float_as_uint(As[cur][mr + 8][k0 + qd + 4]);
                }
            }
#pragma unroll
            for (int nt = 0; nt < 8; nt++) {
                int nr = wn * 64 + nt * 8 + grp;
                bf[nt][0] = __float_as_uint(Bs[cur][nr][k0 + qd]);
                bf[nt][1] = __float_as_uint(Bs[cur][nr][k0 + qd + 4]);
            }
#pragma unroll
            for (int mt = 0; mt < 2; mt++)
#pragma unroll
                for (int nt = 0; nt < 8; nt++)
                    mma8(c[mt][nt], af[mt], bf[nt]);
        }
        if (more) asm volatile("cp.async.wait_group 0;");
        __syncthreads();
    }

    // Uniform store-target selection (per block, not per element)
    float* baseP; int ldo, csub;
    if (mode == 0)      { baseP = C;     ldo = 128; csub = 0;   }
    else if (bn0 < 384) { baseP = g_QU;  ldo = 384; csub = 0;   }
    else if (bn0 < 640) { baseP = g_KV;  ldo = 256; csub = 384; }
    else                { baseP = C;     ldo = 128; csub = 640; }

#pragma unroll
    for (int mt = 0; mt < 2; mt++)
#pragma unroll
        for (int nt = 0; nt < 8; nt++)
#pragma unroll
            for (int hf = 0; hf < 2; hf++) {
                int row = bm0 + wm * 32 + mt * 16 + grp + hf * 8;
                if (row >= M) continue;
                int col = bn0 + wn * 64 + nt * 8 + qd * 2;
                float2 v2;
                v2.x = c[mt][nt][hf * 2 + 0];
                v2.y = c[mt][nt][hf * 2 + 1];
                if (bias) { v2.x += bias[col]; v2.y += bias[col + 1]; }
                float* cp = baseP + (size_t)row * ldo + (col - csub);
                if (accum) { v2.x += cp[0]; v2.y += cp[1]; }
                *(float2*)cp = v2;
            }
}

// ---------------------------------------------------------------------------
// Fused prep kernel: blocks 0..767 build BcatT column j (+bias), blocks
// 768..895 build BblkT row (j-768). Also zeroes g_cnt and g_cur.
// ---------------------------------------------------------------------------
__global__ __launch_bounds__(128) void prep_k(
    const float* __restrict__ Wq, const float* __restrict__ bq,
    const float* __restrict__ Wk, const float* __restrict__ bk,
    const float* __restrict__ Wv, const float* __restrict__ bv,
    const float* __restrict__ Ws, const float* __restrict__ bs,
    const float* __restrict__ We, int N)
{
    int j = blockIdx.x;
    int r = threadIdx.x;

    for (int i = j * 128 + r; i < N; i += 896 * 128) {
        g_cnt[i] = 0;
        g_cur[i] = 0;
    }

    if (j >= 768) {
        int n = j - 768;   // 0..127
#pragma unroll
        for (int kq = 0; kq < 2; kq++) {
            int k = r + kq * 128;   // 0..255
            float v = 0.f;
            if (k < 128) { if (n < 64)  v = We[k * 128 + n]; }
            else         { if (n >= 64) v = We[(k - 128) * 128 + n]; }
            g_BblkT[n * 256 + k] = __uint_as_float(to_tf32(v));
        }
        return;
    }

    float v;
    if (j < 128) v = Wq[r * 128 + j];
    else if (j < 256) {
        int d = j - 128; const float* w = We + d * 128;
        float s = 0.f;
#pragma unroll
        for (int c = 0; c < 64; c++) s = fmaf(Wq[r * 128 + c], w[c], s);
        v = s;
    } else if (j < 384) {
        int d = j - 256; const float* w = We + d * 128 + 64;
        float s = 0.f;
#pragma unroll
        for (int c = 0; c < 64; c++) s = fmaf(Wq[r * 128 + 64 + c], w[c], s);
        v = s;
    }
    else if (j < 512) v = Wk[r * 128 + (j - 384)];
    else if (j < 640) v = Wv[r * 128 + (j - 512)];
    else              v = Ws[r * 128 + (j - 640)];
    g_BcatT[j * 128 + r] = __uint_as_float(to_tf32(v));

    if (r == 0) {
        float bv2;
        if (j < 128) bv2 = bq[j];
        else if (j < 256) {
            int d = j - 128; const float* w = We + d * 128;
            float s = 0.f;
            for (int c = 0; c < 64; c++) s = fmaf(bq[c], w[c], s);
            bv2 = s;
        } else if (j < 384) {
            int d = j - 256; const float* w = We + d * 128 + 64;
            float s = 0.f;
            for (int c = 0; c < 64; c++) s = fmaf(bq[64 + c], w[c], s);
            bv2 = s;
        }
        else if (j < 512) bv2 = bk[j - 384];
        else if (j < 640) bv2 = bv[j - 512];
        else              bv2 = bs[j - 640];
        g_bcat[j] = bv2;
    }
}

// ---------------------------------------------------------------------------
// Edge binning (counting sort by dst)
// ---------------------------------------------------------------------------
__global__ __launch_bounds__(256) void hist_k(const int* __restrict__ ei, int E)
{
    int i = blockIdx.x * 256 + threadIdx.x;
    if (i < E) atomicAdd(&g_cnt[ei[E + i]], 1);
}

__global__ __launch_bounds__(512) void scan1_k(int N)
{
    __shared__ int sh[512];
    int tid = threadIdx.x;
    int i = blockIdx.x * 512 + tid;
    int v = (i < N) ? g_cnt[i] : 0;
    sh[tid] = v;
    __syncthreads();
#pragma unroll
    for (int o = 1; o < 512; o <<= 1) {
        int t = (tid >= o) ? sh[tid - o] : 0;
        __syncthreads();
        sh[tid] += t;
        __syncthreads();
    }
    if (i < N) g_off[i] = sh[tid] - v;        // exclusive within block
    if (tid == 511) g_bsum[blockIdx.x] = sh[511];
}

__global__ __launch_bounds__(256) void scan2_k(int nb)
{
    __shared__ int sh[256];
    int tid = threadIdx.x;
    int v = (tid < nb) ? g_bsum[tid] : 0;
    sh[tid] = v;
    __syncthreads();
#pragma unroll
    for (int o = 1; o < 256; o <<= 1) {
        int t = (tid >= o) ? sh[tid - o] : 0;
        __syncthreads();
        sh[tid] += t;
        __syncthreads();
    }
    if (tid < nb) g_bsum[tid] = sh[tid] - v;  // exclusive block offsets
}

__global__ __launch_bounds__(256) void scatter_k(
    const int* __restrict__ ei, const float* __restrict__ lu,
    const float* __restrict__ tt, int E)
{
    int e = blockIdx.x * 256 + threadIdx.x;
    if (e >= E) return;
    int src = ei[e];
    int dst = ei[E + e];
    int base = g_off[dst] + g_bsum[dst >> 9];
    int pos = base + atomicAdd(&g_cur[dst], 1);
    g_edges[pos] = make_int2(src, e);
    g_relt[pos] = lu[src] - tt[e];
}

// ---------------------------------------------------------------------------
// Aggregation: warp per dst node, 64-thread blocks (fine-grain imbalance
// release). relt precomputed by scatter.
// ---------------------------------------------------------------------------
__device__ __forceinline__ float coss(float x) {
    float k = rintf(x * 0.15915494309189535f);
    float r = fmaf(k, -6.28125f, x);
    r = fmaf(k, -1.93530717958623e-3f, r);
    return __cosf(r);
}
__device__ __forceinline__ float dot4(float4 a, float4 b) {
    return a.x * b.x + a.y * b.y + a.z * b.z + a.w * b.w;
}
__device__ __forceinline__ float4 fma4(float s, float4 a, float4 acc) {
    acc.x = fmaf(s, a.x, acc.x);
    acc.y = fmaf(s, a.y, acc.y);
    acc.z = fmaf(s, a.z, acc.z);
    acc.w = fmaf(s, a.w, acc.w);
    return acc;
}

__global__ __launch_bounds__(64) void agg_k(
    const float* __restrict__ msg,
    const float* __restrict__ wt, const float* __restrict__ bt,
    float* __restrict__ out, int N)
{
    int n = (int)((blockIdx.x * 64 + threadIdx.x) >> 5);
    int lane = threadIdx.x & 31;
    if (n >= N) return;

    int off = g_off[n] + g_bsum[n >> 9];
    int deg = g_cnt[n];

    const float4* QU4 = (const float4*)(g_QU + (size_t)n * 384);
    float4 q4 = QU4[lane];
    float4 u0 = QU4[32 + lane];
    float4 u1 = QU4[64 + lane];

    float4 w4 = make_float4(0.f, 0.f, 0.f, 0.f), b4 = w4;
    if (lane < 16) {
        w4 = ((const float4*)wt)[lane];
        b4 = ((const float4*)bt)[lane];
    }

    float4 av = make_float4(0.f, 0.f, 0.f, 0.f);
    float4 A0 = av, A1 = av;
    float den0 = 0.f, den1 = 0.f;

    int2 se = make_int2(0, 0);
    float rel = 0.f;
    float4 kk = av, vv = av, mg = av;
    if (deg > 0) {
        se = g_edges[off];
        rel = g_relt[off];
        const float4* KV4 = (const float4*)(g_KV + (size_t)se.x * 256);
        kk = KV4[lane]; vv = KV4[32 + lane];
        if (lane >= 16) mg = ((const float4*)(msg + (size_t)se.y * 64))[lane - 16];
    }

    for (int i = 0; i < deg; i++) {
        int2 se2 = se; float rel2 = 0.f;
        float4 kk2 = av, vv2 = av, mg2 = av;
        bool more = (i + 1 < deg);
        if (more) {
            se2 = g_edges[off + i + 1];
            rel2 = g_relt[off + i + 1];
            const float4* KV4 = (const float4*)(g_KV + (size_t)se2.x * 256);
            kk2 = KV4[lane]; vv2 = KV4[32 + lane];
            if (lane >= 16) mg2 = ((const float4*)(msg + (size_t)se2.y * 64))[lane - 16];
        }

        float4 ea;
        if (lane < 16) {
            ea.x = coss(fmaf(rel, w4.x, b4.x));
            ea.y = coss(fmaf(rel, w4.y, b4.y));
            ea.z = coss(fmaf(rel, w4.z, b4.z));
            ea.w = coss(fmaf(rel, w4.w, b4.w));
        } else {
            ea = mg;
        }

        float pqk = dot4(q4, kk);
        float s0 = dot4(ea, u0) + (lane < 16 ? pqk : 0.f);
        float s1 = dot4(ea, u1) + (lane < 16 ? 0.f : pqk);
#pragma unroll
        for (int o = 16; o; o >>= 1) {
            s0 += __shfl_xor_sync(0xffffffffu, s0, o);
            s1 += __shfl_xor_sync(0xffffffffu, s1, o);
        }

        float ex0 = __expf(s0 * 0.125f);
        float ex1 = __expf(s1 * 0.125f);
        den0 += ex0;
        den1 += ex1;

        float evv = (lane < 16) ? ex0 : ex1;
        av = fma4(evv, vv, av);
        A0 = fma4(ex0, ea, A0);
        A1 = fma4(ex1, ea, A1);

        se = se2; rel = rel2; kk = kk2; vv = vv2; mg = mg2;
    }

    float inv0 = 1.f / (den0 + 1e-16f);
    float inv1 = 1.f / (den1 + 1e-16f);
    float invv = (lane < 16) ? inv0 : inv1;

    // out already holds skip; add normalized v-part (sole writer per row)
    float4* op = ((float4*)out) + (size_t)n * 32 + lane;
    float4 o = *op;
    o.x += av.x * invv; o.y += av.y * invv;
    o.z += av.z * invv; o.w += av.w * invv;
    *op = o;

    // store e-accumulators tf32-pre-rounded (epilogue GEMM runs cvtA=0)
    float4 W0, W1;
    W0.x = __uint_as_float(to_tf32(A0.x * inv0));
    W0.y = __uint_as_float(to_tf32(A0.y * inv0));
    W0.z = __uint_as_float(to_tf32(A0.z * inv0));
    W0.w = __uint_as_float(to_tf32(A0.w * inv0));
    W1.x = __uint_as_float(to_tf32(A1.x * inv1));
    W1.y = __uint_as_float(to_tf32(A1.y * inv1));
    W1.z = __uint_as_float(to_tf32(A1.z * inv1));
    W1.w = __uint_as_float(to_tf32(A1.w * inv1));
    float4* acc4 = (float4*)(g_acc + (size_t)n * 256);
    acc4[lane]      = W0;
    acc4[32 + lane] = W1;
}

// ---------------------------------------------------------------------------
extern "C" void kernel_launch(void* const* d_in, const int* in_sizes, int n_in,
                              void* d_out, int out_size)
{
    const float* x    = (const float*)d_in[0];
    const float* lu   = (const float*)d_in[1];
    const int*   ei   = (const int*)  d_in[2];
    const float* tt   = (const float*)d_in[3];
    const float* msg  = (const float*)d_in[4];
    const float* wt   = (const float*)d_in[5];
    const float* bt   = (const float*)d_in[6];
    const float* Wq   = (const float*)d_in[7];
    const float* bq   = (const float*)d_in[8];
    const float* Wk   = (const float*)d_in[9];
    const float* bk   = (const float*)d_in[10];
    const float* Wv   = (const float*)d_in[11];
    const float* bv   = (const float*)d_in[12];
    const float* We   = (const float*)d_in[13];
    const float* Ws   = (const float*)d_in[14];
    const float* bs   = (const float*)d_in[15];
    float* out = (float*)d_out;

    int N = in_sizes[1];
    int E = in_sizes[3];

    float *pacc, *pBcatT, *pbcat, *pBblkT;
    cudaGetSymbolAddress((void**)&pacc,   g_acc);
    cudaGetSymbolAddress((void**)&pBcatT, g_BcatT);
    cudaGetSymbolAddress((void**)&pbcat,  g_bcat);
    cudaGetSymbolAddress((void**)&pBblkT, g_BblkT);

    int gm = (N + 127) / 128;
    int nb = (N + 511) / 512;

    prep_k<<<896, 128>>>(Wq, bq, Wk, bk, Wv, bv, Ws, bs, We, N);   // 0
    hist_k<<<(E + 255) / 256, 256>>>(ei, E);                       // 1
    scan1_k<<<nb, 512>>>(N);                                       // 2
    scan2_k<<<1, 256>>>(nb);                                       // 3
    scatter_k<<<(E + 255) / 256, 256>>>(ei, lu, tt, E);            // 4
    // Projection (tf32): [q|u0|u1|k|v|skip] = x @ Bcat + bcat  (split write)
    mma_gemm<<<dim3(gm, 6), 256>>>(x, 128, pBcatT, 128, out,       // 5 (profiled)
                                   N, 128, pbcat, 0, 1, 1);
    // Aggregation (warp per dst node, 2 warps/block), adds v-part into out
    agg_k<<<(N + 1) / 2, 64>>>(msg, wt, bt, out, N);               // 6
    // Epilogue (tf32, CVT-free): out += accE[N x 256] @ Bblk[256 x 128]
    mma_gemm<<<dim3(gm, 1), 256>>>(pacc, 256, pBblkT, 256, out,    // 7
                                   N, 256, nullptr, 1, 0, 0);
}

// round 10
// speedup vs baseline: 2.2611x; 1.0175x over previous
#include <cuda_runtime.h>
#include <math.h>
#include <stdint.h>

#define MAX_N 100000
#define MAX_E 600000

__device__ float g_QU  [(size_t)MAX_N * 384];  // q(128)|u0(128)|u1(128)
__device__ float g_KV  [(size_t)MAX_N * 256];  // k(128)|v(128)
__device__ float g_acc [(size_t)MAX_N * 256];  // normalized e-accumulators (tf32-rounded)
__device__ float g_BcatT[768 * 128];           // [n][k], tf32-rounded, k-permuted
__device__ float g_bcat[768];
__device__ float g_BblkT[128 * 256];           // [n][k], tf32-rounded, k-permuted
__device__ int   g_cnt[MAX_N];
__device__ int   g_off[MAX_N];
__device__ int   g_cur[MAX_N];
__device__ int   g_bsum[256];
__device__ int2  g_edges[MAX_E];               // (src, e) grouped by dst
__device__ float g_relt[MAX_E];                // lu[src]-t[e], same order

// k-permutation within 8-groups: (qd, qd+4) pairs become adjacent.
__device__ __host__ __forceinline__ int kperm(int k) {
    return (k & ~7) | ((k & 3) << 1) | ((k >> 2) & 1);
}

// ---------------------------------------------------------------------------
// PTX helpers
// ---------------------------------------------------------------------------
__device__ __forceinline__ void cpz(unsigned dst, const void* src, int sz) {
    asm volatile("cp.async.cg.shared.global [%0], [%1], 16, %2;"
                 :: "r"(dst), "l"(src), "r"(sz));
}
__device__ __forceinline__ uint32_t to_tf32(float x) {
    uint32_t u; asm("cvt.rna.tf32.f32 %0, %1;" : "=r"(u) : "f"(x)); return u;
}
__device__ __forceinline__ void mma8(float* c, const uint32_t* a, const uint32_t* b) {
    asm volatile("mma.sync.aligned.m16n8k8.row.col.f32.tf32.tf32.f32 "
        "{%0,%1,%2,%3}, {%4,%5,%6,%7}, {%8,%9}, {%0,%1,%2,%3};"
        : "+f"(c[0]), "+f"(c[1]), "+f"(c[2]), "+f"(c[3])
        : "r"(a[0]), "r"(a[1]), "r"(a[2]), "r"(a[3]), "r"(b[0]), "r"(b[1]));
}

// ---------------------------------------------------------------------------
// tf32 GEMM. C[M x (128*gridDim.y)] = A[M x K] @ B (+bias)(+=C)
// BM=128, BN=128, BK=16, 256 thr (8 warps, 4x2), warp tile 64x64, m16n8k8.
// BT[n][k] pre-rounded tf32, k-permuted: B fragments load as float2 (LDS.64).
// Split-write target resolved uniformly per block.
// ---------------------------------------------------------------------------
__global__ __launch_bounds__(256) void mma_gemm(
    const float* __restrict__ A, int lda,
    const float* __restrict__ BT, int ldb,
    float* __restrict__ C,
    int M, int K,
    const float* __restrict__ bias, int accum, int mode, int cvtA)
{
    __shared__ float As[2][128][20];
    __shared__ float Bs[2][128][20];
    const int tid = threadIdx.x;
    const int lane = tid & 31;
    const int warp = tid >> 5;
    const int wm = warp & 3, wn = warp >> 2;
    const int grp = lane >> 2, qd = lane & 3;
    const int bm0 = blockIdx.x * 128;
    const int bn0 = blockIdx.y * 128;

    float c[2][8][4];
#pragma unroll
    for (int i = 0; i < 2; i++)
#pragma unroll
        for (int j = 0; j < 8; j++)
#pragma unroll
            for (int u = 0; u < 4; u++) c[i][j][u] = 0.f;

    const int ntiles = K >> 4;

    auto cpA = [&](int kt, int buf) {
#pragma unroll
        for (int it = 0; it < 2; it++) {
            int idx = tid + 256 * it;
            int row = idx >> 2, ch = (idx & 3) * 4;
            int gr = bm0 + row;
            int grc = gr < M ? gr : (M - 1);
            const float* src = A + (size_t)grc * lda + kt * 16 + ch;
            unsigned dst = (unsigned)__cvta_generic_to_shared(&As[buf][row][ch]);
            cpz(dst, src, gr < M ? 16 : 0);
        }
    };
    auto cpB = [&](int kt, int buf) {
#pragma unroll
        for (int it = 0; it < 2; it++) {
            int idx = tid + 256 * it;
            int row = idx >> 2, ch = (idx & 3) * 4;
            const float* src = BT + (size_t)(bn0 + row) * ldb + kt * 16 + ch;
            unsigned dst = (unsigned)__cvta_generic_to_shared(&Bs[buf][row][ch]);
            cpz(dst, src, 16);
        }
    };

    cpA(0, 0); cpB(0, 0);
    asm volatile("cp.async.commit_group;");
    asm volatile("cp.async.wait_group 0;");
    __syncthreads();

    for (int t = 0; t < ntiles; t++) {
        int cur = t & 1, nxt = cur ^ 1;
        bool more = (t + 1 < ntiles);
        if (more) {
            cpA(t + 1, nxt); cpB(t + 1, nxt);
            asm volatile("cp.async.commit_group;");
        }
#pragma unroll
        for (int k8 = 0; k8 < 2; k8++) {
            int k0 = k8 * 8;
            uint32_t af[2][4], bf[8][2];
#pragma unroll
            for (int mt = 0; mt < 2; mt++) {
                int mr = wm * 32 + mt * 16 + grp;
                if (cvtA) {
                    af[mt][0] = to_tf32(As[cur][mr    ][k0 + qd]);
                    af[mt][1] = to_tf32(As[cur][mr + 8][k0 + qd]);
                    af[mt][2] = to_tf32(As[cur][mr    ][k0 + qd + 4]);
                    af[mt][3] = to_tf32(As[cur][mr + 8][k0 + qd + 4]);
                } else {
                    af[mt][0] = __float_as_uint(As[cur][mr    ][k0 + qd]);
                    af[mt][1] = __float_as_uint(As[cur][mr + 8][k0 + qd]);
                    af[mt][2] = __float_as_uint(As[cur][mr    ][k0 + qd + 4]);
                    af[mt][3] = __float_as_uint(As[cur][mr + 8][k0 + qd + 4]);
                }
            }
#pragma unroll
            for (int nt = 0; nt < 8; nt++) {
                int nr = wn * 64 + nt * 8 + grp;
                // k-permuted B: (qd, qd+4) adjacent -> single LDS.64
                float2 b2 = *(const float2*)&Bs[cur][nr][k0 + qd * 2];
                bf[nt][0] = __float_as_uint(b2.x);
                bf[nt][1] = __float_as_uint(b2.y);
            }
#pragma unroll
            for (int mt = 0; mt < 2; mt++)
#pragma unroll
                for (int nt = 0; nt < 8; nt++)
                    mma8(c[mt][nt], af[mt], bf[nt]);
        }
        if (more) asm volatile("cp.async.wait_group 0;");
        __syncthreads();
    }

    // Uniform store-target selection (per block)
    float* baseP; int ldo, csub;
    if (mode == 0)      { baseP = C;     ldo = 128; csub = 0;   }
    else if (bn0 < 384) { baseP = g_QU;  ldo = 384; csub = 0;   }
    else if (bn0 < 640) { baseP = g_KV;  ldo = 256; csub = 384; }
    else                { baseP = C;     ldo = 128; csub = 640; }

#pragma unroll
    for (int mt = 0; mt < 2; mt++)
#pragma unroll
        for (int nt = 0; nt < 8; nt++)
#pragma unroll
            for (int hf = 0; hf < 2; hf++) {
                int row = bm0 + wm * 32 + mt * 16 + grp + hf * 8;
                if (row >= M) continue;
                int col = bn0 + wn * 64 + nt * 8 + qd * 2;
                float2 v2;
                v2.x = c[mt][nt][hf * 2 + 0];
                v2.y = c[mt][nt][hf * 2 + 1];
                if (bias) { v2.x += bias[col]; v2.y += bias[col + 1]; }
                float* cp = baseP + (size_t)row * ldo + (col - csub);
                if (accum) { v2.x += cp[0]; v2.y += cp[1]; }
                *(float2*)cp = v2;
            }
}

// ---------------------------------------------------------------------------
// Fused prep: blocks 0..767 build BcatT col j (k-permuted) + bias, blocks
// 768..895 build BblkT row (j-768) (k-permuted). Zeroes g_cnt/g_cur.
// ---------------------------------------------------------------------------
__global__ __launch_bounds__(128) void prep_k(
    const float* __restrict__ Wq, const float* __restrict__ bq,
    const float* __restrict__ Wk, const float* __restrict__ bk,
    const float* __restrict__ Wv, const float* __restrict__ bv,
    const float* __restrict__ Ws, const float* __restrict__ bs,
    const float* __restrict__ We, int N)
{
    int j = blockIdx.x;
    int r = threadIdx.x;

    for (int i = j * 128 + r; i < N; i += 896 * 128) {
        g_cnt[i] = 0;
        g_cur[i] = 0;
    }

    if (j >= 768) {
        int n = j - 768;   // 0..127
#pragma unroll
        for (int kq = 0; kq < 2; kq++) {
            int k = r + kq * 128;   // 0..255
            float v = 0.f;
            if (k < 128) { if (n < 64)  v = We[k * 128 + n]; }
            else         { if (n >= 64) v = We[(k - 128) * 128 + n]; }
            g_BblkT[n * 256 + kperm(k)] = __uint_as_float(to_tf32(v));
        }
        return;
    }

    float v;
    if (j < 128) v = Wq[r * 128 + j];
    else if (j < 256) {
        int d = j - 128; const float* w = We + d * 128;
        float s = 0.f;
#pragma unroll
        for (int c = 0; c < 64; c++) s = fmaf(Wq[r * 128 + c], w[c], s);
        v = s;
    } else if (j < 384) {
        int d = j - 256; const float* w = We + d * 128 + 64;
        float s = 0.f;
#pragma unroll
        for (int c = 0; c < 64; c++) s = fmaf(Wq[r * 128 + 64 + c], w[c], s);
        v = s;
    }
    else if (j < 512) v = Wk[r * 128 + (j - 384)];
    else if (j < 640) v = Wv[r * 128 + (j - 512)];
    else              v = Ws[r * 128 + (j - 640)];
    g_BcatT[j * 128 + kperm(r)] = __uint_as_float(to_tf32(v));

    if (r == 0) {
        float bv2;
        if (j < 128) bv2 = bq[j];
        else if (j < 256) {
            int d = j - 128; const float* w = We + d * 128;
            float s = 0.f;
            for (int c = 0; c < 64; c++) s = fmaf(bq[c], w[c], s);
            bv2 = s;
        } else if (j < 384) {
            int d = j - 256; const float* w = We + d * 128 + 64;
            float s = 0.f;
            for (int c = 0; c < 64; c++) s = fmaf(bq[64 + c], w[c], s);
            bv2 = s;
        }
        else if (j < 512) bv2 = bk[j - 384];
        else if (j < 640) bv2 = bv[j - 512];
        else              bv2 = bs[j - 640];
        g_bcat[j] = bv2;
    }
}

// ---------------------------------------------------------------------------
// Edge binning (counting sort by dst)
// ---------------------------------------------------------------------------
__global__ __launch_bounds__(256) void hist_k(const int* __restrict__ ei, int E)
{
    int i = blockIdx.x * 256 + threadIdx.x;
    if (i < E) atomicAdd(&g_cnt[ei[E + i]], 1);
}

__global__ __launch_bounds__(512) void scan1_k(int N)
{
    __shared__ int sh[512];
    int tid = threadIdx.x;
    int i = blockIdx.x * 512 + tid;
    int v = (i < N) ? g_cnt[i] : 0;
    sh[tid] = v;
    __syncthreads();
#pragma unroll
    for (int o = 1; o < 512; o <<= 1) {
        int t = (tid >= o) ? sh[tid - o] : 0;
        __syncthreads();
        sh[tid] += t;
        __syncthreads();
    }
    if (i < N) g_off[i] = sh[tid] - v;
    if (tid == 511) g_bsum[blockIdx.x] = sh[511];
}

__global__ __launch_bounds__(256) void scan2_k(int nb)
{
    __shared__ int sh[256];
    int tid = threadIdx.x;
    int v = (tid < nb) ? g_bsum[tid] : 0;
    sh[tid] = v;
    __syncthreads();
#pragma unroll
    for (int o = 1; o < 256; o <<= 1) {
        int t = (tid >= o) ? sh[tid - o] : 0;
        __syncthreads();
        sh[tid] += t;
        __syncthreads();
    }
    if (tid < nb) g_bsum[tid] = sh[tid] - v;
}

__global__ __launch_bounds__(256) void scatter_k(
    const int* __restrict__ ei, const float* __restrict__ lu,
    const float* __restrict__ tt, int E)
{
    int e = blockIdx.x * 256 + threadIdx.x;
    if (e >= E) return;
    int src = ei[e];
    int dst = ei[E + e];
    int base = g_off[dst] + g_bsum[dst >> 9];
    int pos = base + atomicAdd(&g_cur[dst], 1);
    g_edges[pos] = make_int2(src, e);
    g_relt[pos] = lu[src] - tt[e];
}

// ---------------------------------------------------------------------------
// Aggregation: one warp per dst node, 32-thread blocks.
// ---------------------------------------------------------------------------
__device__ __forceinline__ float coss(float x) {
    float k = rintf(x * 0.15915494309189535f);
    float r = fmaf(k, -6.28125f, x);
    r = fmaf(k, -1.93530717958623e-3f, r);
    return __cosf(r);
}
__device__ __forceinline__ float dot4(float4 a, float4 b) {
    return a.x * b.x + a.y * b.y + a.z * b.z + a.w * b.w;
}
__device__ __forceinline__ float4 fma4(float s, float4 a, float4 acc) {
    acc.x = fmaf(s, a.x, acc.x);
    acc.y = fmaf(s, a.y, acc.y);
    acc.z = fmaf(s, a.z, acc.z);
    acc.w = fmaf(s, a.w, acc.w);
    return acc;
}

__global__ __launch_bounds__(32) void agg_k(
    const float* __restrict__ msg,
    const float* __restrict__ wt, const float* __restrict__ bt,
    float* __restrict__ out, int N)
{
    int n = blockIdx.x;
    int lane = threadIdx.x;
    if (n >= N) return;

    int off = g_off[n] + g_bsum[n >> 9];
    int deg = g_cnt[n];

    const float4* QU4 = (const float4*)(g_QU + (size_t)n * 384);
    float4 q4 = QU4[lane];
    float4 u0 = QU4[32 + lane];
    float4 u1 = QU4[64 + lane];

    float4 w4 = make_float4(0.f, 0.f, 0.f, 0.f), b4 = w4;
    if (lane < 16) {
        w4 = ((const float4*)wt)[lane];
        b4 = ((const float4*)bt)[lane];
    }

    float4 av = make_float4(0.f, 0.f, 0.f, 0.f);
    float4 A0 = av, A1 = av;
    float den0 = 0.f, den1 = 0.f;

    int2 se = make_int2(0, 0);
    float rel = 0.f;
    float4 kk = av, vv = av, mg = av;
    if (deg > 0) {
        se = g_edges[off];
        rel = g_relt[off];
        const float4* KV4 = (const float4*)(g_KV + (size_t)se.x * 256);
        kk = KV4[lane]; vv = KV4[32 + lane];
        if (lane >= 16) mg = ((const float4*)(msg + (size_t)se.y * 64))[lane - 16];
    }

    for (int i = 0; i < deg; i++) {
        int2 se2 = se; float rel2 = 0.f;
        float4 kk2 = av, vv2 = av, mg2 = av;
        bool more = (i + 1 < deg);
        if (more) {
            se2 = g_edges[off + i + 1];
            rel2 = g_relt[off + i + 1];
            const float4* KV4 = (const float4*)(g_KV + (size_t)se2.x * 256);
            kk2 = KV4[lane]; vv2 = KV4[32 + lane];
            if (lane >= 16) mg2 = ((const float4*)(msg + (size_t)se2.y * 64))[lane - 16];
        }

        float4 ea;
        if (lane < 16) {
            ea.x = coss(fmaf(rel, w4.x, b4.x));
            ea.y = coss(fmaf(rel, w4.y, b4.y));
            ea.z = coss(fmaf(rel, w4.z, b4.z));
            ea.w = coss(fmaf(rel, w4.w, b4.w));
        } else {
            ea = mg;
        }

        float pqk = dot4(q4, kk);
        float s0 = dot4(ea, u0) + (lane < 16 ? pqk : 0.f);
        float s1 = dot4(ea, u1) + (lane < 16 ? 0.f : pqk);
#pragma unroll
        for (int o = 16; o; o >>= 1) {
            s0 += __shfl_xor_sync(0xffffffffu, s0, o);
            s1 += __shfl_xor_sync(0xffffffffu, s1, o);
        }

        float ex0 = __expf(s0 * 0.125f);
        float ex1 = __expf(s1 * 0.125f);
        den0 += ex0;
        den1 += ex1;

        float evv = (lane < 16) ? ex0 : ex1;
        av = fma4(evv, vv, av);
        A0 = fma4(ex0, ea, A0);
        A1 = fma4(ex1, ea, A1);

        se = se2; rel = rel2; kk = kk2; vv = vv2; mg = mg2;
    }

    float inv0 = 1.f / (den0 + 1e-16f);
    float inv1 = 1.f / (den1 + 1e-16f);
    float invv = (lane < 16) ? inv0 : inv1;

    // out already holds skip; add normalized v-part (sole writer per row)
    float4* op = ((float4*)out) + (size_t)n * 32 + lane;
    float4 o = *op;
    o.x += av.x * invv; o.y += av.y * invv;
    o.z += av.z * invv; o.w += av.w * invv;
    *op = o;

    // store e-accumulators tf32-pre-rounded (epilogue GEMM runs cvtA=0)
    float4 W0, W1;
    W0.x = __uint_as_float(to_tf32(A0.x * inv0));
    W0.y = __uint_as_float(to_tf32(A0.y * inv0));
    W0.z = __uint_as_float(to_tf32(A0.z * inv0));
    W0.w = __uint_as_float(to_tf32(A0.w * inv0));
    W1.x = __uint_as_float(to_tf32(A1.x * inv1));
    W1.y = __uint_as_float(to_tf32(A1.y * inv1));
    W1.z = __uint_as_float(to_tf32(A1.z * inv1));
    W1.w = __uint_as_float(to_tf32(A1.w * inv1));
    float4* acc4 = (float4*)(g_acc + (size_t)n * 256);
    acc4[lane]      = W0;
    acc4[32 + lane] = W1;
}

// ---------------------------------------------------------------------------
extern "C" void kernel_launch(void* const* d_in, const int* in_sizes, int n_in,
                              void* d_out, int out_size)
{
    const float* x    = (const float*)d_in[0];
    const float* lu   = (const float*)d_in[1];
    const int*   ei   = (const int*)  d_in[2];
    const float* tt   = (const float*)d_in[3];
    const float* msg  = (const float*)d_in[4];
    const float* wt   = (const float*)d_in[5];
    const float* bt   = (const float*)d_in[6];
    const float* Wq   = (const float*)d_in[7];
    const float* bq   = (const float*)d_in[8];
    const float* Wk   = (const float*)d_in[9];
    const float* bk   = (const float*)d_in[10];
    const float* Wv   = (const float*)d_in[11];
    const float* bv   = (const float*)d_in[12];
    const float* We   = (const float*)d_in[13];
    const float* Ws   = (const float*)d_in[14];
    const float* bs   = (const float*)d_in[15];
    float* out = (float*)d_out;

    int N = in_sizes[1];
    int E = in_sizes[3];

    float *pacc, *pBcatT, *pbcat, *pBblkT;
    cudaGetSymbolAddress((void**)&pacc,   g_acc);
    cudaGetSymbolAddress((void**)&pBcatT, g_BcatT);
    cudaGetSymbolAddress((void**)&pbcat,  g_bcat);
    cudaGetSymbolAddress((void**)&pBblkT, g_BblkT);

    int gm = (N + 127) / 128;
    int nb = (N + 511) / 512;

    prep_k<<<896, 128>>>(Wq, bq, Wk, bk, Wv, bv, Ws, bs, We, N);   // 0
    hist_k<<<(E + 255) / 256, 256>>>(ei, E);                       // 1
    scan1_k<<<nb, 512>>>(N);                                       // 2
    scan2_k<<<1, 256>>>(nb);                                       // 3
    scatter_k<<<(E + 255) / 256, 256>>>(ei, lu, tt, E);            // 4
    // Projection (tf32): [q|u0|u1|k|v|skip] = x @ Bcat + bcat  (split write)
    mma_gemm<<<dim3(gm, 6), 256>>>(x, 128, pBcatT, 128, out,       // 5
                                   N, 128, pbcat, 0, 1, 1);
    // Aggregation (1 warp per dst node), adds v-part into out
    agg_k<<<N, 32>>>(msg, wt, bt, out, N);                         // 6
    // Epilogue (tf32, CVT-free): out += accE[N x 256] @ Bblk[256 x 128]
    mma_gemm<<<dim3(gm, 1), 256>>>(pacc, 256, pBblkT, 256, out,    // 7
                                   N, 256, nullptr, 1, 0, 0);
}